// round 1
// baseline (speedup 1.0000x reference)
#include <cuda_runtime.h>
#include <math.h>

#define N_NODES 50000
#define N_EDGES 800000
#define EMB 128
#define NH 8

// ---- scratch (static __device__, allocation-free) ----
__device__ float    g_S[N_NODES * EMB];      // Ws(nodes)+b  ("edges" term)
__device__ float    g_R[N_NODES * EMB];      // Wr(nodes)+b
__device__ float    g_logit[N_EDGES * NH];   // logits, then unnormalized exp
__device__ unsigned g_max[N_NODES * NH];     // ordered-uint encoded segment max
__device__ float    g_denom[N_NODES * NH];

// monotone float<->uint encoding for atomicMax on floats
__device__ __forceinline__ unsigned ord_enc(float f) {
    unsigned u = __float_as_uint(f);
    return (u & 0x80000000u) ? ~u : (u | 0x80000000u);
}
__device__ __forceinline__ float ord_dec(unsigned e) {
    return (e & 0x80000000u) ? __uint_as_float(e ^ 0x80000000u)
                             : __uint_as_float(~e);
}

__device__ __forceinline__ float mish_f(float x) {
    float sp = (x > 20.f) ? x : log1pf(__expf(x));
    return x * tanhf(sp);
}

// ---- kernel 0: zero/init scratch + output ----
__global__ void k_init(float* __restrict__ out) {
    int i = blockIdx.x * blockDim.x + threadIdx.x;
    int stride = gridDim.x * blockDim.x;
    for (int j = i; j < N_NODES * EMB; j += stride) out[j] = 0.f;
    for (int j = i; j < N_NODES * NH; j += stride) {
        g_denom[j] = 0.f;
        g_max[j]   = 0u;   // encodes most-negative float
    }
}

// ---- kernel 1: fused SGEMM  [N,128] x [128,256] -> g_S | g_R ----
// block: 256 threads, tile 32 rows x 256 cols, BK=16
__global__ void k_gemm(const float* __restrict__ A,
                       const float* __restrict__ Ws, const float* __restrict__ Wr,
                       const float* __restrict__ Wsb, const float* __restrict__ Wrb) {
    __shared__ float As[32][17];
    __shared__ float Wt[16][256];
    int tid  = threadIdx.x;
    int row0 = blockIdx.x * 32;
    int tcol = tid & 63;   // 64 col-groups of 4 cols
    int trow = tid >> 6;   // 4 row-groups of 8 rows

    float acc[8][4] = {};

    for (int k0 = 0; k0 < 128; k0 += 16) {
        // A tile [32][16]
        for (int i = tid; i < 32 * 16; i += 256) {
            int r = i >> 4, c = i & 15;
            int gr = row0 + r;
            As[r][c] = (gr < N_NODES) ? A[gr * 128 + k0 + c] : 0.f;
        }
        // W tile [16][256] via float4 (cols<128 from Ws, else Wr)
        for (int i = tid; i < 16 * 64; i += 256) {
            int kr = i >> 6;
            int c4 = (i & 63) * 4;
            const float* src = (c4 < 128) ? (Ws + (k0 + kr) * 128 + c4)
                                          : (Wr + (k0 + kr) * 128 + (c4 - 128));
            float4 v = *(const float4*)src;
            *(float4*)&Wt[kr][c4] = v;
        }
        __syncthreads();
#pragma unroll
        for (int k = 0; k < 16; k++) {
            float a[8];
#pragma unroll
            for (int i = 0; i < 8; i++) a[i] = As[trow * 8 + i][k];
            float4 wv = *(float4*)&Wt[k][tcol * 4];
            float w[4] = {wv.x, wv.y, wv.z, wv.w};
#pragma unroll
            for (int i = 0; i < 8; i++)
#pragma unroll
                for (int j = 0; j < 4; j++) acc[i][j] += a[i] * w[j];
        }
        __syncthreads();
    }

    int c0 = tcol * 4;
    float b[4];
#pragma unroll
    for (int j = 0; j < 4; j++) {
        int cc = c0 + j;
        b[j] = (cc < 128) ? Wsb[cc] : Wrb[cc - 128];
    }
#pragma unroll
    for (int i = 0; i < 8; i++) {
        int gr = row0 + trow * 8 + i;
        if (gr < N_NODES) {
#pragma unroll
            for (int j = 0; j < 4; j++) {
                int cc = c0 + j;
                float v = acc[i][j] + b[j];
                if (cc < 128) g_S[gr * 128 + cc] = v;
                else          g_R[gr * 128 + (cc - 128)] = v;
            }
        }
    }
}

// ---- kernel 2: per-edge logits + segment max (1 warp / edge) ----
__global__ void k_logit(const int* __restrict__ senders,
                        const int* __restrict__ receivers,
                        const float* __restrict__ attn_k,
                        const float* __restrict__ attn_b) {
    int warp = threadIdx.x >> 5;
    int lane = threadIdx.x & 31;
    int e = blockIdx.x * 8 + warp;
    if (e >= N_EDGES) return;

    int s = senders[e];
    int r = receivers[e];

    float4 sv = ((const float4*)g_S)[s * 32 + lane];
    float4 rv = ((const float4*)g_R)[r * 32 + lane];
    // lane covers features [lane*4 .. lane*4+3], all in head lane>>2,
    // head-dim index d0 = (lane*4) & 15 = (lane&3)*4
    float4 ak = *(const float4*)(attn_k + (lane & 3) * 4);

    float sum = mish_f(sv.x + rv.x) * ak.x
              + mish_f(sv.y + rv.y) * ak.y
              + mish_f(sv.z + rv.z) * ak.z
              + mish_f(sv.w + rv.w) * ak.w;
    sum += __shfl_xor_sync(0xFFFFFFFFu, sum, 1);
    sum += __shfl_xor_sync(0xFFFFFFFFu, sum, 2);

    if ((lane & 3) == 0) {
        int h = lane >> 2;
        float logit = sum + attn_b[0];
        g_logit[e * 8 + h] = logit;
        atomicMax(&g_max[r * 8 + h], ord_enc(logit));
    }
}

// ---- kernel 3: exp(logit - max) + segment sum ----
__global__ void k_expden(const int* __restrict__ receivers) {
    int i = blockIdx.x * blockDim.x + threadIdx.x;
    if (i >= N_EDGES * NH) return;
    int e = i >> 3, h = i & 7;
    int r = receivers[e];
    float m = ord_dec(g_max[r * 8 + h]);
    float u = __expf(g_logit[i] - m);
    g_logit[i] = u;
    atomicAdd(&g_denom[r * 8 + h], u);
}

// ---- kernel 4: weighted scatter-add (1 warp / edge, vector RED) ----
__global__ void k_agg(const int* __restrict__ senders,
                      const int* __restrict__ receivers,
                      float* __restrict__ out) {
    int warp = threadIdx.x >> 5;
    int lane = threadIdx.x & 31;
    int e = blockIdx.x * 8 + warp;
    if (e >= N_EDGES) return;

    int s = senders[e];
    int r = receivers[e];
    int h = lane >> 2;
    float u   = g_logit[e * 8 + h];
    float den = g_denom[r * 8 + h];
    float w = u / den;

    float4 sv = ((const float4*)g_S)[s * 32 + lane];
    float* p = out + r * 128 + lane * 4;
    asm volatile("red.global.add.v4.f32 [%0], {%1,%2,%3,%4};" ::
                 "l"(p), "f"(sv.x * w), "f"(sv.y * w), "f"(sv.z * w), "f"(sv.w * w)
                 : "memory");
}

extern "C" void kernel_launch(void* const* d_in, const int* in_sizes, int n_in,
                              void* d_out, int out_size) {
    const float* nodes     = (const float*)d_in[0];
    const int*   senders   = (const int*)  d_in[1];
    const int*   receivers = (const int*)  d_in[2];
    const float* Ws_k      = (const float*)d_in[3];
    const float* Ws_b      = (const float*)d_in[4];
    const float* Wr_k      = (const float*)d_in[5];
    const float* Wr_b      = (const float*)d_in[6];
    const float* attn_k    = (const float*)d_in[7];
    const float* attn_b    = (const float*)d_in[8];
    float* out = (float*)d_out;

    k_init<<<(N_NODES * EMB + 255) / 256, 256>>>(out);
    k_gemm<<<(N_NODES + 31) / 32, 256>>>(nodes, Ws_k, Wr_k, Ws_b, Wr_b);
    k_logit<<<N_EDGES / 8, 256>>>(senders, receivers, attn_k, attn_b);
    k_expden<<<(N_EDGES * NH + 255) / 256, 256>>>(receivers);
    k_agg<<<N_EDGES / 8, 256>>>(senders, receivers, out);
}

// round 2
// speedup vs baseline: 1.5137x; 1.5137x over previous
#include <cuda_runtime.h>
#include <math.h>

#define N_NODES 50000
#define N_EDGES 800000
#define EMB 128
#define NH 8

// ---- scratch (static __device__, allocation-free) ----
__device__ float    g_S[N_NODES * EMB];      // Ws(nodes)+b  ("edges" term)
__device__ float    g_R[N_NODES * EMB];      // Wr(nodes)+b
__device__ float    g_logit[N_EDGES * NH];   // logits, then unnormalized exp
__device__ unsigned g_max[N_NODES * NH];     // ordered-uint encoded segment max
__device__ float    g_denom[N_NODES * NH];

// monotone float<->uint encoding for atomicMax on floats
__device__ __forceinline__ unsigned ord_enc(float f) {
    unsigned u = __float_as_uint(f);
    return (u & 0x80000000u) ? ~u : (u | 0x80000000u);
}
__device__ __forceinline__ float ord_dec(unsigned e) {
    return (e & 0x80000000u) ? __uint_as_float(e ^ 0x80000000u)
                             : __uint_as_float(~e);
}

// fast mish: tanh(softplus(x)) = ((1+e^x)^2 - 1) / ((1+e^x)^2 + 1)
// 1 MUFU.EX2 + 1 MUFU.RCP + few FFMA. Clamp exp arg at 20: for x>20 the
// formula returns x*~1.0 which equals mish(x) to fp32 precision anyway.
__device__ __forceinline__ float mish_f(float x) {
    float u = __expf(fminf(x, 20.f));
    float v = u * u + 2.f * u;          // (1+u)^2 - 1
    return x * __fdividef(v, v + 2.f);  // x * (v)/(v+2) = x*tanh(softplus)
}

// ---- kernel 0: zero/init scratch + output ----
__global__ void k_init(float* __restrict__ out) {
    int i = blockIdx.x * blockDim.x + threadIdx.x;
    int stride = gridDim.x * blockDim.x;
    for (int j = i; j < N_NODES * EMB; j += stride) out[j] = 0.f;
    for (int j = i; j < N_NODES * NH; j += stride) {
        g_denom[j] = 0.f;
        g_max[j]   = 0u;   // encodes most-negative float
    }
}

// ---- kernel 1: SGEMM [50000,128] x [128,128] -> g_S (y=0) / g_R (y=1) ----
// 128x128 tile, 256 threads, 8x8 register microtile, BK=8.
__global__ void __launch_bounds__(256, 2)
k_gemm(const float* __restrict__ A,
       const float* __restrict__ Ws, const float* __restrict__ Wr,
       const float* __restrict__ Wsb, const float* __restrict__ Wrb) {
    __shared__ float As[8][128];   // transposed A tile: As[k][row]
    __shared__ float Bs[8][128];   // Bs[k][col]

    const float* W  = blockIdx.y == 0 ? Ws  : Wr;
    const float* Wb = blockIdx.y == 0 ? Wsb : Wrb;
    float* O        = blockIdx.y == 0 ? g_S : g_R;

    int tid  = threadIdx.x;
    int row0 = blockIdx.x * 128;
    int tx = tid & 15;            // col group
    int ty = tid >> 4;            // row group
    int rb = ty * 8;              // thread row base in tile
    int cb = tx * 8;              // thread col base in tile

    // A-load mapping: each thread loads one float4 per chunk
    int ar  = tid >> 1;           // 0..127
    int ac4 = (tid & 1) * 4;      // 0 or 4
    int a_row = row0 + ar;
    bool a_ok = a_row < N_NODES;
    // B-load mapping
    int bkr = tid >> 5;           // 0..7
    int bc4 = (tid & 31) * 4;     // 0..124

    float acc[8][8];
#pragma unroll
    for (int i = 0; i < 8; i++)
#pragma unroll
        for (int j = 0; j < 8; j++) acc[i][j] = 0.f;

    for (int k0 = 0; k0 < 128; k0 += 8) {
        float4 av = a_ok ? *(const float4*)(A + a_row * 128 + k0 + ac4)
                         : make_float4(0.f, 0.f, 0.f, 0.f);
        float4 bv = *(const float4*)(W + (k0 + bkr) * 128 + bc4);
        As[ac4 + 0][ar] = av.x;
        As[ac4 + 1][ar] = av.y;
        As[ac4 + 2][ar] = av.z;
        As[ac4 + 3][ar] = av.w;
        *(float4*)&Bs[bkr][bc4] = bv;
        __syncthreads();

#pragma unroll
        for (int kk = 0; kk < 8; kk++) {
            float4 a0 = *(float4*)&As[kk][rb];
            float4 a1 = *(float4*)&As[kk][rb + 4];
            float4 b0 = *(float4*)&Bs[kk][cb];
            float4 b1 = *(float4*)&Bs[kk][cb + 4];
            float a[8] = {a0.x, a0.y, a0.z, a0.w, a1.x, a1.y, a1.z, a1.w};
            float b[8] = {b0.x, b0.y, b0.z, b0.w, b1.x, b1.y, b1.z, b1.w};
#pragma unroll
            for (int i = 0; i < 8; i++)
#pragma unroll
                for (int j = 0; j < 8; j++) acc[i][j] += a[i] * b[j];
        }
        __syncthreads();
    }

    float bias[8];
#pragma unroll
    for (int j = 0; j < 8; j++) bias[j] = Wb[cb + j];

#pragma unroll
    for (int i = 0; i < 8; i++) {
        int gr = row0 + rb + i;
        if (gr < N_NODES) {
            float4 o0 = make_float4(acc[i][0] + bias[0], acc[i][1] + bias[1],
                                    acc[i][2] + bias[2], acc[i][3] + bias[3]);
            float4 o1 = make_float4(acc[i][4] + bias[4], acc[i][5] + bias[5],
                                    acc[i][6] + bias[6], acc[i][7] + bias[7]);
            *(float4*)(O + gr * 128 + cb)     = o0;
            *(float4*)(O + gr * 128 + cb + 4) = o1;
        }
    }
}

// ---- kernel 2: per-edge logits + segment max (1 warp / edge) ----
__global__ void k_logit(const int* __restrict__ senders,
                        const int* __restrict__ receivers,
                        const float* __restrict__ attn_k,
                        const float* __restrict__ attn_b) {
    int warp = threadIdx.x >> 5;
    int lane = threadIdx.x & 31;
    int e = blockIdx.x * 8 + warp;
    if (e >= N_EDGES) return;

    int s = senders[e];
    int r = receivers[e];

    float4 sv = ((const float4*)g_S)[s * 32 + lane];
    float4 rv = ((const float4*)g_R)[r * 32 + lane];
    float4 ak = *(const float4*)(attn_k + (lane & 3) * 4);

    float sum = mish_f(sv.x + rv.x) * ak.x
              + mish_f(sv.y + rv.y) * ak.y
              + mish_f(sv.z + rv.z) * ak.z
              + mish_f(sv.w + rv.w) * ak.w;
    sum += __shfl_xor_sync(0xFFFFFFFFu, sum, 1);
    sum += __shfl_xor_sync(0xFFFFFFFFu, sum, 2);

    if ((lane & 3) == 0) {
        int h = lane >> 2;
        float logit = sum + attn_b[0];
        g_logit[e * 8 + h] = logit;
        atomicMax(&g_max[r * 8 + h], ord_enc(logit));
    }
}

// ---- kernel 3: exp(logit - max) + segment sum ----
__global__ void k_expden(const int* __restrict__ receivers) {
    int i = blockIdx.x * blockDim.x + threadIdx.x;
    if (i >= N_EDGES * NH) return;
    int e = i >> 3, h = i & 7;
    int r = receivers[e];
    float m = ord_dec(g_max[r * 8 + h]);
    float u = __expf(g_logit[i] - m);
    g_logit[i] = u;
    atomicAdd(&g_denom[r * 8 + h], u);
}

// ---- kernel 4: weighted scatter-add (1 warp / edge, vector RED) ----
__global__ void k_agg(const int* __restrict__ senders,
                      const int* __restrict__ receivers,
                      float* __restrict__ out) {
    int warp = threadIdx.x >> 5;
    int lane = threadIdx.x & 31;
    int e = blockIdx.x * 8 + warp;
    if (e >= N_EDGES) return;

    int s = senders[e];
    int r = receivers[e];
    int h = lane >> 2;
    float u   = g_logit[e * 8 + h];
    float den = g_denom[r * 8 + h];
    float w = __fdividef(u, den);

    float4 sv = ((const float4*)g_S)[s * 32 + lane];
    float* p = out + r * 128 + lane * 4;
    asm volatile("red.global.add.v4.f32 [%0], {%1,%2,%3,%4};" ::
                 "l"(p), "f"(sv.x * w), "f"(sv.y * w), "f"(sv.z * w), "f"(sv.w * w)
                 : "memory");
}

extern "C" void kernel_launch(void* const* d_in, const int* in_sizes, int n_in,
                              void* d_out, int out_size) {
    const float* nodes     = (const float*)d_in[0];
    const int*   senders   = (const int*)  d_in[1];
    const int*   receivers = (const int*)  d_in[2];
    const float* Ws_k      = (const float*)d_in[3];
    const float* Ws_b      = (const float*)d_in[4];
    const float* Wr_k      = (const float*)d_in[5];
    const float* Wr_b      = (const float*)d_in[6];
    const float* attn_k    = (const float*)d_in[7];
    const float* attn_b    = (const float*)d_in[8];
    float* out = (float*)d_out;

    k_init<<<(N_NODES * EMB + 255) / 256, 256>>>(out);
    dim3 ggrid((N_NODES + 127) / 128, 2);
    k_gemm<<<ggrid, 256>>>(nodes, Ws_k, Wr_k, Ws_b, Wr_b);
    k_logit<<<N_EDGES / 8, 256>>>(senders, receivers, attn_k, attn_b);
    k_expden<<<(N_EDGES * NH + 255) / 256, 256>>>(receivers);
    k_agg<<<N_EDGES / 8, 256>>>(senders, receivers, out);
}

// round 3
// speedup vs baseline: 1.6131x; 1.0657x over previous
#include <cuda_runtime.h>
#include <math.h>

#define N_NODES 50000
#define N_EDGES 800000
#define EMB 128
#define NH 8

// ---- scratch (static __device__, allocation-free) ----
__device__ float g_S[N_NODES * EMB];      // Ws(nodes)+b  ("edges" term)
__device__ float g_R[N_NODES * EMB];      // Wr(nodes)+b
__device__ float g_u[N_EDGES * NH];       // unnormalized softmax numerators
__device__ float g_denom[N_NODES * NH];

// fast mish: tanh(softplus(x)) = ((1+e^x)^2 - 1) / ((1+e^x)^2 + 1)
// 1 MUFU.EX2 + 1 MUFU.RCP + few FFMA. Clamp exp arg at 20: for x>20 the
// formula returns x*~1.0 which equals mish(x) to fp32 precision anyway.
__device__ __forceinline__ float mish_f(float x) {
    float u = __expf(fminf(x, 20.f));
    float v = u * u + 2.f * u;          // (1+u)^2 - 1
    return x * __fdividef(v, v + 2.f);  // x * v/(v+2) = x*tanh(softplus(x))
}

// ---- kernel 0: zero output + denom ----
__global__ void k_init(float* __restrict__ out) {
    int i = blockIdx.x * blockDim.x + threadIdx.x;
    int stride = gridDim.x * blockDim.x;
    for (int j = i; j < N_NODES * EMB; j += stride) out[j] = 0.f;
    for (int j = i; j < N_NODES * NH; j += stride) g_denom[j] = 0.f;
}

// ---- kernel 1: SGEMM [50000,128] x [128,128] -> g_S (y=0) / g_R (y=1) ----
// 128x128 tile, 256 threads, 8x8 register microtile, BK=8.
__global__ void __launch_bounds__(256, 2)
k_gemm(const float* __restrict__ A,
       const float* __restrict__ Ws, const float* __restrict__ Wr,
       const float* __restrict__ Wsb, const float* __restrict__ Wrb) {
    __shared__ float As[8][128];   // transposed A tile: As[k][row]
    __shared__ float Bs[8][128];   // Bs[k][col]

    const float* W  = blockIdx.y == 0 ? Ws  : Wr;
    const float* Wb = blockIdx.y == 0 ? Wsb : Wrb;
    float* O        = blockIdx.y == 0 ? g_S : g_R;

    int tid  = threadIdx.x;
    int row0 = blockIdx.x * 128;
    int tx = tid & 15;            // col group
    int ty = tid >> 4;            // row group
    int rb = ty * 8;              // thread row base in tile
    int cb = tx * 8;              // thread col base in tile

    int ar  = tid >> 1;           // 0..127
    int ac4 = (tid & 1) * 4;      // 0 or 4
    int a_row = row0 + ar;
    bool a_ok = a_row < N_NODES;
    int bkr = tid >> 5;           // 0..7
    int bc4 = (tid & 31) * 4;     // 0..124

    float acc[8][8];
#pragma unroll
    for (int i = 0; i < 8; i++)
#pragma unroll
        for (int j = 0; j < 8; j++) acc[i][j] = 0.f;

    for (int k0 = 0; k0 < 128; k0 += 8) {
        float4 av = a_ok ? *(const float4*)(A + a_row * 128 + k0 + ac4)
                         : make_float4(0.f, 0.f, 0.f, 0.f);
        float4 bv = *(const float4*)(W + (k0 + bkr) * 128 + bc4);
        As[ac4 + 0][ar] = av.x;
        As[ac4 + 1][ar] = av.y;
        As[ac4 + 2][ar] = av.z;
        As[ac4 + 3][ar] = av.w;
        *(float4*)&Bs[bkr][bc4] = bv;
        __syncthreads();

#pragma unroll
        for (int kk = 0; kk < 8; kk++) {
            float4 a0 = *(float4*)&As[kk][rb];
            float4 a1 = *(float4*)&As[kk][rb + 4];
            float4 b0 = *(float4*)&Bs[kk][cb];
            float4 b1 = *(float4*)&Bs[kk][cb + 4];
            float a[8] = {a0.x, a0.y, a0.z, a0.w, a1.x, a1.y, a1.z, a1.w};
            float b[8] = {b0.x, b0.y, b0.z, b0.w, b1.x, b1.y, b1.z, b1.w};
#pragma unroll
            for (int i = 0; i < 8; i++)
#pragma unroll
                for (int j = 0; j < 8; j++) acc[i][j] += a[i] * b[j];
        }
        __syncthreads();
    }

    float bias[8];
#pragma unroll
    for (int j = 0; j < 8; j++) bias[j] = Wb[cb + j];

#pragma unroll
    for (int i = 0; i < 8; i++) {
        int gr = row0 + rb + i;
        if (gr < N_NODES) {
            float4 o0 = make_float4(acc[i][0] + bias[0], acc[i][1] + bias[1],
                                    acc[i][2] + bias[2], acc[i][3] + bias[3]);
            float4 o1 = make_float4(acc[i][4] + bias[4], acc[i][5] + bias[5],
                                    acc[i][6] + bias[6], acc[i][7] + bias[7]);
            *(float4*)(O + gr * 128 + cb)     = o0;
            *(float4*)(O + gr * 128 + cb + 4) = o1;
        }
    }
}

// ---- kernel 2: per-edge logits -> u = exp(logit), denom += u ----
// Shift-free softmax: per-segment max subtraction cancels in u/denom;
// logits are O(10) so direct exp is exact to fp32 roundoff (clamp@60 guard).
__global__ void k_logit(const int* __restrict__ senders,
                        const int* __restrict__ receivers,
                        const float* __restrict__ attn_k,
                        const float* __restrict__ attn_b) {
    int warp = threadIdx.x >> 5;
    int lane = threadIdx.x & 31;
    int e = blockIdx.x * 8 + warp;
    if (e >= N_EDGES) return;

    int s = senders[e];
    int r = receivers[e];

    float4 sv = ((const float4*)g_S)[s * 32 + lane];
    float4 rv = ((const float4*)g_R)[r * 32 + lane];
    float4 ak = *(const float4*)(attn_k + (lane & 3) * 4);

    float sum = mish_f(sv.x + rv.x) * ak.x
              + mish_f(sv.y + rv.y) * ak.y
              + mish_f(sv.z + rv.z) * ak.z
              + mish_f(sv.w + rv.w) * ak.w;
    sum += __shfl_xor_sync(0xFFFFFFFFu, sum, 1);
    sum += __shfl_xor_sync(0xFFFFFFFFu, sum, 2);

    if ((lane & 3) == 0) {
        int h = lane >> 2;
        float logit = sum + attn_b[0];
        float u = __expf(fminf(logit, 60.f));
        g_u[e * 8 + h] = u;
        atomicAdd(&g_denom[r * 8 + h], u);
    }
}

// ---- kernel 3: weighted scatter-add (1 warp / edge, vector RED) ----
__global__ void k_agg(const int* __restrict__ senders,
                      const int* __restrict__ receivers,
                      float* __restrict__ out) {
    int warp = threadIdx.x >> 5;
    int lane = threadIdx.x & 31;
    int e = blockIdx.x * 8 + warp;
    if (e >= N_EDGES) return;

    int s = senders[e];
    int r = receivers[e];
    int h = lane >> 2;
    float u   = g_u[e * 8 + h];
    float den = g_denom[r * 8 + h];
    float w = __fdividef(u, den);

    float4 sv = ((const float4*)g_S)[s * 32 + lane];
    float* p = out + r * 128 + lane * 4;
    asm volatile("red.global.add.v4.f32 [%0], {%1,%2,%3,%4};" ::
                 "l"(p), "f"(sv.x * w), "f"(sv.y * w), "f"(sv.z * w), "f"(sv.w * w)
                 : "memory");
}

extern "C" void kernel_launch(void* const* d_in, const int* in_sizes, int n_in,
                              void* d_out, int out_size) {
    const float* nodes     = (const float*)d_in[0];
    const int*   senders   = (const int*)  d_in[1];
    const int*   receivers = (const int*)  d_in[2];
    const float* Ws_k      = (const float*)d_in[3];
    const float* Ws_b      = (const float*)d_in[4];
    const float* Wr_k      = (const float*)d_in[5];
    const float* Wr_b      = (const float*)d_in[6];
    const float* attn_k    = (const float*)d_in[7];
    const float* attn_b    = (const float*)d_in[8];
    float* out = (float*)d_out;

    k_init<<<(N_NODES * EMB + 255) / 256, 256>>>(out);
    dim3 ggrid((N_NODES + 127) / 128, 2);
    k_gemm<<<ggrid, 256>>>(nodes, Ws_k, Wr_k, Ws_b, Wr_b);
    k_logit<<<N_EDGES / 8, 256>>>(senders, receivers, attn_k, attn_b);
    k_agg<<<N_EDGES / 8, 256>>>(senders, receivers, out);
}

// round 4
// speedup vs baseline: 2.3880x; 1.4804x over previous
#include <cuda_runtime.h>
#include <math.h>

#define N_NODES 50000
#define N_EDGES 800000
#define EMB 128
#define NH 8

// ---- scratch (static __device__, allocation-free) ----
__device__ float g_S[N_NODES * EMB];   // Ws(nodes)+b  ("edges" message)
__device__ float g_R[N_NODES * EMB];   // Wr(nodes)+b
__device__ int   g_csr[N_EDGES];       // sender ids grouped by receiver
__device__ int   g_cnt[N_NODES];       // in-degree
__device__ int   g_off[N_NODES];       // bucket start
__device__ int   g_cur[N_NODES];       // scatter cursor
__device__ int   g_total;

// fast mish: x*tanh(softplus(x)) = x * ((1+e^x)^2-1)/((1+e^x)^2+1)
// 1 MUFU.EX2 + 1 MUFU.RCP + few FFMA; clamp@20 is exact in fp32.
__device__ __forceinline__ float mish_f(float x) {
    float u = __expf(fminf(x, 20.f));
    float v = u * u + 2.f * u;
    return x * __fdividef(v, v + 2.f);
}

// ---- kernel 0: zero counters ----
__global__ void k_zero() {
    int i = blockIdx.x * blockDim.x + threadIdx.x;
    if (i < N_NODES) g_cnt[i] = 0;
    if (i == 0) g_total = 0;
}

// ---- kernel 1: in-degree histogram ----
__global__ void k_hist(const int* __restrict__ receivers) {
    int e = blockIdx.x * blockDim.x + threadIdx.x;
    if (e < N_EDGES) atomicAdd(&g_cnt[receivers[e]], 1);
}

// ---- kernel 2: offset reservation (warp prefix scan + 1 atomic/warp) ----
// Bucket ordering across warps is arbitrary — CSR stays valid.
__global__ void k_reserve() {
    int i = blockIdx.x * blockDim.x + threadIdx.x;
    int lane = threadIdx.x & 31;
    int c = (i < N_NODES) ? g_cnt[i] : 0;
    int x = c;
#pragma unroll
    for (int d = 1; d < 32; d <<= 1) {
        int y = __shfl_up_sync(0xFFFFFFFFu, x, d);
        if (lane >= d) x += y;
    }
    int total = __shfl_sync(0xFFFFFFFFu, x, 31);
    int base = 0;
    if (lane == 31) base = atomicAdd(&g_total, total);
    base = __shfl_sync(0xFFFFFFFFu, base, 31);
    if (i < N_NODES) {
        int off = base + x - c;   // exclusive prefix within warp
        g_off[i] = off;
        g_cur[i] = off;
    }
}

// ---- kernel 3: scatter sender ids into CSR buckets ----
__global__ void k_scatter(const int* __restrict__ senders,
                          const int* __restrict__ receivers) {
    int e = blockIdx.x * blockDim.x + threadIdx.x;
    if (e < N_EDGES) {
        int pos = atomicAdd(&g_cur[receivers[e]], 1);
        g_csr[pos] = senders[e];
    }
}

// ---- kernel 4: SGEMM [50000,128] x [128,128] -> g_S (y=0) / g_R (y=1) ----
__global__ void __launch_bounds__(256, 2)
k_gemm(const float* __restrict__ A,
       const float* __restrict__ Ws, const float* __restrict__ Wr,
       const float* __restrict__ Wsb, const float* __restrict__ Wrb) {
    __shared__ float As[8][128];
    __shared__ float Bs[8][128];

    const float* W  = blockIdx.y == 0 ? Ws  : Wr;
    const float* Wb = blockIdx.y == 0 ? Wsb : Wrb;
    float* O        = blockIdx.y == 0 ? g_S : g_R;

    int tid  = threadIdx.x;
    int row0 = blockIdx.x * 128;
    int tx = tid & 15;
    int ty = tid >> 4;
    int rb = ty * 8;
    int cb = tx * 8;

    int ar  = tid >> 1;
    int ac4 = (tid & 1) * 4;
    int a_row = row0 + ar;
    bool a_ok = a_row < N_NODES;
    int bkr = tid >> 5;
    int bc4 = (tid & 31) * 4;

    float acc[8][8];
#pragma unroll
    for (int i = 0; i < 8; i++)
#pragma unroll
        for (int j = 0; j < 8; j++) acc[i][j] = 0.f;

    for (int k0 = 0; k0 < 128; k0 += 8) {
        float4 av = a_ok ? *(const float4*)(A + a_row * 128 + k0 + ac4)
                         : make_float4(0.f, 0.f, 0.f, 0.f);
        float4 bv = *(const float4*)(W + (k0 + bkr) * 128 + bc4);
        As[ac4 + 0][ar] = av.x;
        As[ac4 + 1][ar] = av.y;
        As[ac4 + 2][ar] = av.z;
        As[ac4 + 3][ar] = av.w;
        *(float4*)&Bs[bkr][bc4] = bv;
        __syncthreads();

#pragma unroll
        for (int kk = 0; kk < 8; kk++) {
            float4 a0 = *(float4*)&As[kk][rb];
            float4 a1 = *(float4*)&As[kk][rb + 4];
            float4 b0 = *(float4*)&Bs[kk][cb];
            float4 b1 = *(float4*)&Bs[kk][cb + 4];
            float a[8] = {a0.x, a0.y, a0.z, a0.w, a1.x, a1.y, a1.z, a1.w};
            float b[8] = {b0.x, b0.y, b0.z, b0.w, b1.x, b1.y, b1.z, b1.w};
#pragma unroll
            for (int i = 0; i < 8; i++)
#pragma unroll
                for (int j = 0; j < 8; j++) acc[i][j] += a[i] * b[j];
        }
        __syncthreads();
    }

    float bias[8];
#pragma unroll
    for (int j = 0; j < 8; j++) bias[j] = Wb[cb + j];

#pragma unroll
    for (int i = 0; i < 8; i++) {
        int gr = row0 + rb + i;
        if (gr < N_NODES) {
            float4 o0 = make_float4(acc[i][0] + bias[0], acc[i][1] + bias[1],
                                    acc[i][2] + bias[2], acc[i][3] + bias[3]);
            float4 o1 = make_float4(acc[i][4] + bias[4], acc[i][5] + bias[5],
                                    acc[i][6] + bias[6], acc[i][7] + bias[7]);
            *(float4*)(O + gr * 128 + cb)     = o0;
            *(float4*)(O + gr * 128 + cb + 4) = o1;
        }
    }
}

// ---- kernel 5: fused softmax + aggregate, one warp per receiver node ----
// agg = (sum_e u_e * S[s_e]) / (sum_e u_e); u_e = exp(logit_e) (shift-free,
// logits O(10) << 88, clamp@60 guard). R[r] stays in registers; S gathered
// once per edge and reused for both logit and accumulation. No atomics.
__global__ void __launch_bounds__(256)
k_fused(const float* __restrict__ attn_k,
        const float* __restrict__ attn_b,
        float* __restrict__ out) {
    int warp = threadIdx.x >> 5;
    int lane = threadIdx.x & 31;
    int n = blockIdx.x * 8 + warp;
    if (n >= N_NODES) return;

    int off = g_off[n];
    int deg = g_cnt[n];

    float4 rv = ((const float4*)g_R)[n * 32 + lane];
    float4 ak = *(const float4*)(attn_k + (lane & 3) * 4);
    float  ab = attn_b[0];

    float4 acc = make_float4(0.f, 0.f, 0.f, 0.f);
    float  den = 0.f;

    if (deg > 0) {
        // 1-deep software pipeline for MLP=2 on the gather chain
        int s = g_csr[off];
        float4 sv = ((const float4*)g_S)[s * 32 + lane];
        for (int i = 0; i < deg; i++) {
            float4 svn;
            if (i + 1 < deg) {
                int s2 = g_csr[off + i + 1];
                svn = ((const float4*)g_S)[s2 * 32 + lane];
            }
            float t = mish_f(sv.x + rv.x) * ak.x
                    + mish_f(sv.y + rv.y) * ak.y
                    + mish_f(sv.z + rv.z) * ak.z
                    + mish_f(sv.w + rv.w) * ak.w;
            t += __shfl_xor_sync(0xFFFFFFFFu, t, 1);
            t += __shfl_xor_sync(0xFFFFFFFFu, t, 2);   // all 4 lanes of head have sum
            float u = __expf(fminf(t + ab, 60.f));
            acc.x += u * sv.x;
            acc.y += u * sv.y;
            acc.z += u * sv.z;
            acc.w += u * sv.w;
            den += u;
            sv = svn;
        }
    }

    float inv = (deg > 0) ? __fdividef(1.f, den) : 0.f;
    float4 o = make_float4(acc.x * inv, acc.y * inv, acc.z * inv, acc.w * inv);
    ((float4*)out)[n * 32 + lane] = o;
}

extern "C" void kernel_launch(void* const* d_in, const int* in_sizes, int n_in,
                              void* d_out, int out_size) {
    const float* nodes     = (const float*)d_in[0];
    const int*   senders   = (const int*)  d_in[1];
    const int*   receivers = (const int*)  d_in[2];
    const float* Ws_k      = (const float*)d_in[3];
    const float* Ws_b      = (const float*)d_in[4];
    const float* Wr_k      = (const float*)d_in[5];
    const float* Wr_b      = (const float*)d_in[6];
    const float* attn_k    = (const float*)d_in[7];
    const float* attn_b    = (const float*)d_in[8];
    float* out = (float*)d_out;

    k_zero<<<(N_NODES + 255) / 256, 256>>>();
    k_hist<<<(N_EDGES + 255) / 256, 256>>>(receivers);
    k_reserve<<<(N_NODES + 255) / 256, 256>>>();
    k_scatter<<<(N_EDGES + 255) / 256, 256>>>(senders, receivers);
    dim3 ggrid((N_NODES + 127) / 128, 2);
    k_gemm<<<ggrid, 256>>>(nodes, Ws_k, Wr_k, Ws_b, Wr_b);
    k_fused<<<(N_NODES + 7) / 8, 256>>>(attn_k, attn_b, out);
}

// round 5
// speedup vs baseline: 2.4143x; 1.0110x over previous
#include <cuda_runtime.h>
#include <math.h>

#define N_NODES 50000
#define N_EDGES 800000
#define EMB 128
#define NH 8

// ---- scratch (static __device__, allocation-free) ----
__device__ float g_S[N_NODES * EMB];   // Ws(nodes)+b  ("edges" message)
__device__ float g_R[N_NODES * EMB];   // Wr(nodes)+b
__device__ int   g_csr[N_EDGES];       // sender ids grouped by receiver
__device__ int   g_cnt[N_NODES];       // in-degree
__device__ int   g_off[N_NODES];       // bucket start
__device__ int   g_cur[N_NODES];       // scatter cursor
__device__ int   g_total;

// fast mish: x*tanh(softplus(x)) = x*((1+e^x)^2-1)/((1+e^x)^2+1)
// 1 MUFU.EX2 + 1 MUFU.RCP + few FFMA; clamp@20 exact in fp32.
__device__ __forceinline__ float mish_f(float x) {
    float u = __expf(fminf(x, 20.f));
    float v = u * u + 2.f * u;
    return x * __fdividef(v, v + 2.f);
}

// ---- packed f32x2 helpers (Blackwell 2xFP32 pipe) ----
__device__ __forceinline__ unsigned long long bcast2(float x) {
    unsigned long long r;
    asm("mov.b64 %0, {%1, %1};" : "=l"(r) : "f"(x));
    return r;
}
__device__ __forceinline__ void fma2(unsigned long long& d,
                                     unsigned long long a,
                                     unsigned long long b) {
    asm("fma.rn.f32x2 %0, %1, %2, %0;" : "+l"(d) : "l"(a), "l"(b));
}

// ---- kernel 0: zero counters ----
__global__ void k_zero() {
    int i = blockIdx.x * blockDim.x + threadIdx.x;
    if (i < N_NODES) g_cnt[i] = 0;
    if (i == 0) g_total = 0;
}

// ---- kernel 1: in-degree histogram (2 edges/thread) ----
__global__ void k_hist(const int* __restrict__ receivers) {
    int e = (blockIdx.x * blockDim.x + threadIdx.x) * 2;
    if (e < N_EDGES) {
        int2 r = *(const int2*)(receivers + e);
        atomicAdd(&g_cnt[r.x], 1);
        atomicAdd(&g_cnt[r.y], 1);
    }
}

// ---- kernel 2: offset reservation (warp scan + 1 atomic/warp) ----
__global__ void k_reserve() {
    int i = blockIdx.x * blockDim.x + threadIdx.x;
    int lane = threadIdx.x & 31;
    int c = (i < N_NODES) ? g_cnt[i] : 0;
    int x = c;
#pragma unroll
    for (int d = 1; d < 32; d <<= 1) {
        int y = __shfl_up_sync(0xFFFFFFFFu, x, d);
        if (lane >= d) x += y;
    }
    int total = __shfl_sync(0xFFFFFFFFu, x, 31);
    int base = 0;
    if (lane == 31) base = atomicAdd(&g_total, total);
    base = __shfl_sync(0xFFFFFFFFu, base, 31);
    if (i < N_NODES) {
        int off = base + x - c;
        g_off[i] = off;
        g_cur[i] = off;
    }
}

// ---- kernel 3: scatter sender ids into CSR buckets (2 edges/thread) ----
__global__ void k_scatter(const int* __restrict__ senders,
                          const int* __restrict__ receivers) {
    int e = (blockIdx.x * blockDim.x + threadIdx.x) * 2;
    if (e < N_EDGES) {
        int2 r = *(const int2*)(receivers + e);
        int2 s = *(const int2*)(senders + e);
        int p0 = atomicAdd(&g_cur[r.x], 1);
        int p1 = atomicAdd(&g_cur[r.y], 1);
        g_csr[p0] = s.x;
        g_csr[p1] = s.y;
    }
}

// ---- kernel 4: SGEMM via packed f32x2 FMA ----
// [50000,128] x [128,128] -> g_S (y=0) / g_R (y=1). 128x128 tile, 8x8 micro.
__global__ void __launch_bounds__(256, 2)
k_gemm(const float* __restrict__ A,
       const float* __restrict__ Ws, const float* __restrict__ Wr,
       const float* __restrict__ Wsb, const float* __restrict__ Wrb) {
    __shared__ float As[8][128];   // As[k][row]
    __shared__ float Bs[8][128];   // Bs[k][col]

    const float* W  = blockIdx.y == 0 ? Ws  : Wr;
    const float* Wb = blockIdx.y == 0 ? Wsb : Wrb;
    float* O        = blockIdx.y == 0 ? g_S : g_R;

    int tid  = threadIdx.x;
    int row0 = blockIdx.x * 128;
    int tx = tid & 15;
    int ty = tid >> 4;
    int rb = ty * 8;
    int cb = tx * 8;

    int ar  = tid >> 1;
    int ac4 = (tid & 1) * 4;
    int a_row = row0 + ar;
    bool a_ok = a_row < N_NODES;
    int bkr = tid >> 5;
    int bc4 = (tid & 31) * 4;

    // acc2[i][j] holds output cols (cb+2j, cb+2j+1) for row rb+i
    unsigned long long acc2[8][4];
#pragma unroll
    for (int i = 0; i < 8; i++)
#pragma unroll
        for (int j = 0; j < 4; j++) acc2[i][j] = 0ULL;

    for (int k0 = 0; k0 < 128; k0 += 8) {
        float4 av = a_ok ? *(const float4*)(A + a_row * 128 + k0 + ac4)
                         : make_float4(0.f, 0.f, 0.f, 0.f);
        float4 bv = *(const float4*)(W + (k0 + bkr) * 128 + bc4);
        As[ac4 + 0][ar] = av.x;
        As[ac4 + 1][ar] = av.y;
        As[ac4 + 2][ar] = av.z;
        As[ac4 + 3][ar] = av.w;
        *(float4*)&Bs[bkr][bc4] = bv;
        __syncthreads();

#pragma unroll
        for (int kk = 0; kk < 8; kk++) {
            float4 a0 = *(float4*)&As[kk][rb];
            float4 a1 = *(float4*)&As[kk][rb + 4];
            // b pairs come packed for free from 16B loads
            ulonglong2 bp0 = *(ulonglong2*)&Bs[kk][cb];      // cols cb..cb+3
            ulonglong2 bp1 = *(ulonglong2*)&Bs[kk][cb + 4];  // cols cb+4..cb+7
            unsigned long long bp[4] = {bp0.x, bp0.y, bp1.x, bp1.y};
            float a[8] = {a0.x, a0.y, a0.z, a0.w, a1.x, a1.y, a1.z, a1.w};
#pragma unroll
            for (int i = 0; i < 8; i++) {
                unsigned long long ap = bcast2(a[i]);
#pragma unroll
                for (int j = 0; j < 4; j++) fma2(acc2[i][j], ap, bp[j]);
            }
        }
        __syncthreads();
    }

    float bias[8];
#pragma unroll
    for (int j = 0; j < 8; j++) bias[j] = Wb[cb + j];

#pragma unroll
    for (int i = 0; i < 8; i++) {
        int gr = row0 + rb + i;
        if (gr < N_NODES) {
            float2 c0 = *(float2*)&acc2[i][0];
            float2 c1 = *(float2*)&acc2[i][1];
            float2 c2 = *(float2*)&acc2[i][2];
            float2 c3 = *(float2*)&acc2[i][3];
            float4 o0 = make_float4(c0.x + bias[0], c0.y + bias[1],
                                    c1.x + bias[2], c1.y + bias[3]);
            float4 o1 = make_float4(c2.x + bias[4], c2.y + bias[5],
                                    c3.x + bias[6], c3.y + bias[7]);
            *(float4*)(O + gr * 128 + cb)     = o0;
            *(float4*)(O + gr * 128 + cb + 4) = o1;
        }
    }
}

// ---- kernel 5: fused softmax + aggregate, one warp per receiver node ----
// agg = (sum_e u_e*S[s_e]) / (sum_e u_e), u = exp(logit) shift-free.
// 2-deep S prefetch + 3-deep csr-index prefetch to break the
// LDG(csr)->LDG(S) serial latency chain.
__global__ void __launch_bounds__(256)
k_fused(const float* __restrict__ attn_k,
        const float* __restrict__ attn_b,
        float* __restrict__ out) {
    int warp = threadIdx.x >> 5;
    int lane = threadIdx.x & 31;
    int n = blockIdx.x * 8 + warp;
    if (n >= N_NODES) return;

    int off = g_off[n];
    int deg = g_cnt[n];

    float4 rv = ((const float4*)g_R)[n * 32 + lane];
    float4 ak = *(const float4*)(attn_k + (lane & 3) * 4);
    float  ab = attn_b[0];

    float4 acc = make_float4(0.f, 0.f, 0.f, 0.f);
    float  den = 0.f;

    if (deg > 0) {
        int s0 = g_csr[off];
        int s1 = (deg > 1) ? g_csr[off + 1] : 0;
        int s2 = (deg > 2) ? g_csr[off + 2] : 0;
        float4 sv  = ((const float4*)g_S)[s0 * 32 + lane];
        float4 svn = (deg > 1) ? ((const float4*)g_S)[s1 * 32 + lane]
                               : make_float4(0.f, 0.f, 0.f, 0.f);
        for (int i = 0; i < deg; i++) {
            float4 svn2 = make_float4(0.f, 0.f, 0.f, 0.f);
            if (i + 2 < deg) svn2 = ((const float4*)g_S)[s2 * 32 + lane];
            int s3 = (i + 3 < deg) ? g_csr[off + i + 3] : 0;

            float t = mish_f(sv.x + rv.x) * ak.x
                    + mish_f(sv.y + rv.y) * ak.y
                    + mish_f(sv.z + rv.z) * ak.z
                    + mish_f(sv.w + rv.w) * ak.w;
            t += __shfl_xor_sync(0xFFFFFFFFu, t, 1);
            t += __shfl_xor_sync(0xFFFFFFFFu, t, 2);
            float u = __expf(fminf(t + ab, 60.f));
            acc.x += u * sv.x;
            acc.y += u * sv.y;
            acc.z += u * sv.z;
            acc.w += u * sv.w;
            den += u;

            sv = svn; svn = svn2; s2 = s3;
        }
    }

    float inv = (deg > 0) ? __fdividef(1.f, den) : 0.f;
    ((float4*)out)[n * 32 + lane] =
        make_float4(acc.x * inv, acc.y * inv, acc.z * inv, acc.w * inv);
}

extern "C" void kernel_launch(void* const* d_in, const int* in_sizes, int n_in,
                              void* d_out, int out_size) {
    const float* nodes     = (const float*)d_in[0];
    const int*   senders   = (const int*)  d_in[1];
    const int*   receivers = (const int*)  d_in[2];
    const float* Ws_k      = (const float*)d_in[3];
    const float* Ws_b      = (const float*)d_in[4];
    const float* Wr_k      = (const float*)d_in[5];
    const float* Wr_b      = (const float*)d_in[6];
    const float* attn_k    = (const float*)d_in[7];
    const float* attn_b    = (const float*)d_in[8];
    float* out = (float*)d_out;

    k_zero<<<(N_NODES + 255) / 256, 256>>>();
    k_hist<<<(N_EDGES / 2 + 255) / 256, 256>>>(receivers);
    k_reserve<<<(N_NODES + 255) / 256, 256>>>();
    k_scatter<<<(N_EDGES / 2 + 255) / 256, 256>>>(senders, receivers);
    dim3 ggrid((N_NODES + 127) / 128, 2);
    k_gemm<<<ggrid, 256>>>(nodes, Ws_k, Wr_k, Ws_b, Wr_b);
    k_fused<<<(N_NODES + 7) / 8, 256>>>(attn_k, attn_b, out);
}

// round 6
// speedup vs baseline: 2.5656x; 1.0627x over previous
#include <cuda_runtime.h>
#include <cuda_bf16.h>
#include <math.h>

#define N_NODES 50000
#define N_EDGES 800000
#define EMB 128
#define NH 8

// ---- scratch (static __device__, allocation-free) ----
__device__ float g_S[N_NODES * EMB];   // Ws(nodes)+b
__device__ float g_R[N_NODES * EMB];   // Wr(nodes)+b
__device__ int   g_csr[N_EDGES];
__device__ int   g_cnt[N_NODES];
__device__ int   g_off[N_NODES];
__device__ int   g_cur[N_NODES];
__device__ int   g_total;
// bf16-split weight table, transposed: [n][k], n in 0..255 (0..127 = Ws cols,
// 128..255 = Wr cols), k contiguous.
__device__ __nv_bfloat16 g_Wh[256 * 128];
__device__ __nv_bfloat16 g_Wl[256 * 128];

// fast mish: x*tanh(softplus(x)) = x*((1+e^x)^2-1)/((1+e^x)^2+1)
__device__ __forceinline__ float mish_f(float x) {
    float u = __expf(fminf(x, 20.f));
    float v = u * u + 2.f * u;
    return x * __fdividef(v, v + 2.f);
}

// ---- kernel: zero counters ----
__global__ void k_zero() {
    int i = blockIdx.x * blockDim.x + threadIdx.x;
    if (i < N_NODES) g_cnt[i] = 0;
    if (i == 0) g_total = 0;
}

// ---- kernel: in-degree histogram (2 edges/thread) ----
__global__ void k_hist(const int* __restrict__ receivers) {
    int e = (blockIdx.x * blockDim.x + threadIdx.x) * 2;
    if (e < N_EDGES) {
        int2 r = *(const int2*)(receivers + e);
        atomicAdd(&g_cnt[r.x], 1);
        atomicAdd(&g_cnt[r.y], 1);
    }
}

// ---- kernel: split W into bf16 hi/lo, transposed [n][k] ----
__global__ void k_wsplit(const float* __restrict__ Ws,
                         const float* __restrict__ Wr) {
    int i = blockIdx.x * blockDim.x + threadIdx.x;   // 32768
    if (i >= 256 * 128) return;
    int k = i >> 8;          // 0..127
    int n = i & 255;         // 0..255  (coalesced read over n)
    float w = (n < 128) ? Ws[k * 128 + n] : Wr[k * 128 + (n - 128)];
    __nv_bfloat16 hi = __float2bfloat16(w);
    __nv_bfloat16 lo = __float2bfloat16(w - __bfloat162float(hi));
    g_Wh[n * 128 + k] = hi;
    g_Wl[n * 128 + k] = lo;
}

// ---- bf16 mma.sync helper ----
__device__ __forceinline__ void mma_bf16(float* c, const unsigned* a,
                                         unsigned b0, unsigned b1) {
    asm volatile(
        "mma.sync.aligned.m16n8k16.row.col.f32.bf16.bf16.f32 "
        "{%0,%1,%2,%3}, {%4,%5,%6,%7}, {%8,%9}, {%0,%1,%2,%3};"
        : "+f"(c[0]), "+f"(c[1]), "+f"(c[2]), "+f"(c[3])
        : "r"(a[0]), "r"(a[1]), "r"(a[2]), "r"(a[3]), "r"(b0), "r"(b1));
}

// ---- kernel: tensor-core GEMM, bf16 3-term split ----
// C[50000,256] = A[50000,128] x [Ws|Wr][128,256]; CTA = 64 rows x 256 cols.
// A ~ Ah+Al (bf16); C = Ah*Wh + Ah*Wl + Al*Wh  (AlWl negligible).
#define SA 34   // smem row stride (elements), even for LDS.32
__global__ void __launch_bounds__(256, 2)
k_gemm_tc(const float* __restrict__ A,
          const float* __restrict__ Wsb, const float* __restrict__ Wrb) {
    __shared__ __nv_bfloat16 Ah[64 * SA];
    __shared__ __nv_bfloat16 Al[64 * SA];

    int tid  = threadIdx.x;
    int lane = tid & 31;
    int w    = tid >> 5;
    int wr   = w & 1;        // 2 row groups of 32
    int wc   = w >> 1;       // 4 col groups of 64
    int g    = lane >> 2;
    int t    = lane & 3;
    int row0 = blockIdx.x * 64;

    // A staging map: row = tid>>2, cols q*8..q*8+7 (2 float4)
    int srow = tid >> 2;
    int q8   = (tid & 3) * 8;
    int grow = row0 + srow;
    bool rok = grow < N_NODES;

    float acc[2][8][4];
#pragma unroll
    for (int rt = 0; rt < 2; rt++)
#pragma unroll
        for (int nt = 0; nt < 8; nt++)
#pragma unroll
            for (int j = 0; j < 4; j++) acc[rt][nt][j] = 0.f;

    for (int kc = 0; kc < 4; kc++) {
        int k0 = kc * 32;
        // stage + split A chunk [64][32]
#pragma unroll
        for (int v = 0; v < 2; v++) {
            float4 av = rok ? *(const float4*)(A + grow * 128 + k0 + q8 + v * 4)
                            : make_float4(0.f, 0.f, 0.f, 0.f);
            float h0 = __bfloat162float(__float2bfloat16(av.x));
            float h1 = __bfloat162float(__float2bfloat16(av.y));
            float h2 = __bfloat162float(__float2bfloat16(av.z));
            float h3 = __bfloat162float(__float2bfloat16(av.w));
            int base = srow * SA + q8 + v * 4;
            *(__nv_bfloat162*)&Ah[base]     = __floats2bfloat162_rn(h0, h1);
            *(__nv_bfloat162*)&Ah[base + 2] = __floats2bfloat162_rn(h2, h3);
            *(__nv_bfloat162*)&Al[base]     = __floats2bfloat162_rn(av.x - h0, av.y - h1);
            *(__nv_bfloat162*)&Al[base + 2] = __floats2bfloat162_rn(av.z - h2, av.w - h3);
        }
        __syncthreads();

#pragma unroll
        for (int ks = 0; ks < 2; ks++) {
            int kk = ks * 16 + 2 * t;
            unsigned ah[2][4], al[2][4];
#pragma unroll
            for (int rt = 0; rt < 2; rt++) {
                int r0 = wr * 32 + rt * 16 + g;
                ah[rt][0] = *(unsigned*)&Ah[r0 * SA + kk];
                ah[rt][1] = *(unsigned*)&Ah[(r0 + 8) * SA + kk];
                ah[rt][2] = *(unsigned*)&Ah[r0 * SA + kk + 8];
                ah[rt][3] = *(unsigned*)&Ah[(r0 + 8) * SA + kk + 8];
                al[rt][0] = *(unsigned*)&Al[r0 * SA + kk];
                al[rt][1] = *(unsigned*)&Al[(r0 + 8) * SA + kk];
                al[rt][2] = *(unsigned*)&Al[r0 * SA + kk + 8];
                al[rt][3] = *(unsigned*)&Al[(r0 + 8) * SA + kk + 8];
            }
#pragma unroll
            for (int nt = 0; nt < 8; nt++) {
                int gn = wc * 64 + nt * 8 + g;
                int kg = k0 + ks * 16 + 2 * t;
                unsigned bh0 = *(const unsigned*)(g_Wh + gn * 128 + kg);
                unsigned bh1 = *(const unsigned*)(g_Wh + gn * 128 + kg + 8);
                unsigned bl0 = *(const unsigned*)(g_Wl + gn * 128 + kg);
                unsigned bl1 = *(const unsigned*)(g_Wl + gn * 128 + kg + 8);
#pragma unroll
                for (int rt = 0; rt < 2; rt++) {
                    mma_bf16(acc[rt][nt], ah[rt], bh0, bh1);
                    mma_bf16(acc[rt][nt], ah[rt], bl0, bl1);
                    mma_bf16(acc[rt][nt], al[rt], bh0, bh1);
                }
            }
        }
        __syncthreads();
    }

    // epilogue: bias + store fp32 to g_S / g_R
#pragma unroll
    for (int rt = 0; rt < 2; rt++) {
        int r0 = row0 + wr * 32 + rt * 16 + g;
#pragma unroll
        for (int nt = 0; nt < 8; nt++) {
            int n = wc * 64 + nt * 8 + 2 * t;       // 0..255
            const float* bb = (n < 128) ? Wsb : Wrb;
            int nn = n & 127;
            float b0 = bb[nn], b1 = bb[nn + 1];
            float* O = (n < 128) ? g_S : g_R;
            if (r0 < N_NODES)
                *(float2*)(O + r0 * 128 + nn) =
                    make_float2(acc[rt][nt][0] + b0, acc[rt][nt][1] + b1);
            if (r0 + 8 < N_NODES)
                *(float2*)(O + (r0 + 8) * 128 + nn) =
                    make_float2(acc[rt][nt][2] + b0, acc[rt][nt][3] + b1);
        }
    }
}

// ---- kernel: offset reservation (warp scan + 1 atomic/warp) ----
__global__ void k_reserve() {
    int i = blockIdx.x * blockDim.x + threadIdx.x;
    int lane = threadIdx.x & 31;
    int c = (i < N_NODES) ? g_cnt[i] : 0;
    int x = c;
#pragma unroll
    for (int d = 1; d < 32; d <<= 1) {
        int y = __shfl_up_sync(0xFFFFFFFFu, x, d);
        if (lane >= d) x += y;
    }
    int total = __shfl_sync(0xFFFFFFFFu, x, 31);
    int base = 0;
    if (lane == 31) base = atomicAdd(&g_total, total);
    base = __shfl_sync(0xFFFFFFFFu, base, 31);
    if (i < N_NODES) {
        int off = base + x - c;
        g_off[i] = off;
        g_cur[i] = off;
    }
}

// ---- kernel: scatter sender ids into CSR buckets ----
__global__ void k_scatter(const int* __restrict__ senders,
                          const int* __restrict__ receivers) {
    int e = (blockIdx.x * blockDim.x + threadIdx.x) * 2;
    if (e < N_EDGES) {
        int2 r = *(const int2*)(receivers + e);
        int2 s = *(const int2*)(senders + e);
        int p0 = atomicAdd(&g_cur[r.x], 1);
        int p1 = atomicAdd(&g_cur[r.y], 1);
        g_csr[p0] = s.x;
        g_csr[p1] = s.y;
    }
}

// ---- kernel: fused softmax + aggregate, one warp per receiver node ----
__global__ void __launch_bounds__(256)
k_fused(const float* __restrict__ attn_k,
        const float* __restrict__ attn_b,
        float* __restrict__ out) {
    int warp = threadIdx.x >> 5;
    int lane = threadIdx.x & 31;
    int n = blockIdx.x * 8 + warp;
    if (n >= N_NODES) return;

    int off = g_off[n];
    int deg = g_cnt[n];

    float4 rv = ((const float4*)g_R)[n * 32 + lane];
    float4 ak = *(const float4*)(attn_k + (lane & 3) * 4);
    float  ab = attn_b[0];

    float4 acc = make_float4(0.f, 0.f, 0.f, 0.f);
    float  den = 0.f;

    if (deg > 0) {
        int s0 = g_csr[off];
        int s1 = (deg > 1) ? g_csr[off + 1] : 0;
        int s2 = (deg > 2) ? g_csr[off + 2] : 0;
        float4 sv  = ((const float4*)g_S)[s0 * 32 + lane];
        float4 svn = (deg > 1) ? ((const float4*)g_S)[s1 * 32 + lane]
                               : make_float4(0.f, 0.f, 0.f, 0.f);
        for (int i = 0; i < deg; i++) {
            float4 svn2 = make_float4(0.f, 0.f, 0.f, 0.f);
            if (i + 2 < deg) svn2 = ((const float4*)g_S)[s2 * 32 + lane];
            int s3 = (i + 3 < deg) ? g_csr[off + i + 3] : 0;

            float t = mish_f(sv.x + rv.x) * ak.x
                    + mish_f(sv.y + rv.y) * ak.y
                    + mish_f(sv.z + rv.z) * ak.z
                    + mish_f(sv.w + rv.w) * ak.w;
            t += __shfl_xor_sync(0xFFFFFFFFu, t, 1);
            t += __shfl_xor_sync(0xFFFFFFFFu, t, 2);
            float u = __expf(fminf(t + ab, 60.f));
            acc.x += u * sv.x;
            acc.y += u * sv.y;
            acc.z += u * sv.z;
            acc.w += u * sv.w;
            den += u;

            sv = svn; svn = svn2; s2 = s3;
        }
    }

    float inv = (deg > 0) ? __fdividef(1.f, den) : 0.f;
    ((float4*)out)[n * 32 + lane] =
        make_float4(acc.x * inv, acc.y * inv, acc.z * inv, acc.w * inv);
}

extern "C" void kernel_launch(void* const* d_in, const int* in_sizes, int n_in,
                              void* d_out, int out_size) {
    const float* nodes     = (const float*)d_in[0];
    const int*   senders   = (const int*)  d_in[1];
    const int*   receivers = (const int*)  d_in[2];
    const float* Ws_k      = (const float*)d_in[3];
    const float* Ws_b      = (const float*)d_in[4];
    const float* Wr_k      = (const float*)d_in[5];
    const float* Wr_b      = (const float*)d_in[6];
    const float* attn_k    = (const float*)d_in[7];
    const float* attn_b    = (const float*)d_in[8];
    float* out = (float*)d_out;

    k_zero<<<(N_NODES + 255) / 256, 256>>>();                       // 1
    k_hist<<<(N_EDGES / 2 + 255) / 256, 256>>>(receivers);          // 2
    k_wsplit<<<128, 256>>>(Ws_k, Wr_k);                             // 3
    k_gemm_tc<<<(N_NODES + 63) / 64, 256>>>(nodes, Ws_b, Wr_b);     // 4 <- ncu slot
    k_reserve<<<(N_NODES + 255) / 256, 256>>>();                    // 5
    k_scatter<<<(N_EDGES / 2 + 255) / 256, 256>>>(senders, receivers); // 6
    k_fused<<<(N_NODES + 7) / 8, 256>>>(attn_k, attn_b, out);       // 7
}

// round 7
// speedup vs baseline: 3.2461x; 1.2653x over previous
#include <cuda_runtime.h>
#include <cuda_bf16.h>
#include <math.h>

#define N_NODES 50000
#define N_EDGES 800000
#define EMB 128
#define NH 8

// ---- scratch (static __device__, allocation-free) ----
__device__ float g_S[N_NODES * EMB];   // Ws(nodes)+b
__device__ float g_R[N_NODES * EMB];   // Wr(nodes)+b
__device__ int   g_csr[N_EDGES];
__device__ int   g_cnt[N_NODES];
__device__ int   g_off[N_NODES];
__device__ int   g_cur[N_NODES];
__device__ int   g_total;
// B fragments pre-packed per (wc,kc,ks,nt,lane): {bh0,bh1,bl0,bl1}
// idx = (((wc*4 + kc)*2 + ks)*8 + nt)*32 + lane   -> 8192 uint4 = 128 KB
__device__ uint4 g_Bfrag[4 * 4 * 2 * 8 * 32];

// fast mish: x*tanh(softplus(x)) = x*((1+e^x)^2-1)/((1+e^x)^2+1)
__device__ __forceinline__ float mish_f(float x) {
    float u = __expf(fminf(x, 20.f));
    float v = u * u + 2.f * u;
    return x * __fdividef(v, v + 2.f);
}

// ---- kernel: zero counters ----
__global__ void k_zero() {
    int i = blockIdx.x * blockDim.x + threadIdx.x;
    if (i < N_NODES) g_cnt[i] = 0;
    if (i == 0) g_total = 0;
}

// ---- kernel: in-degree histogram (2 edges/thread) ----
__global__ void k_hist(const int* __restrict__ receivers) {
    int e = (blockIdx.x * blockDim.x + threadIdx.x) * 2;
    if (e < N_EDGES) {
        int2 r = *(const int2*)(receivers + e);
        atomicAdd(&g_cnt[r.x], 1);
        atomicAdd(&g_cnt[r.y], 1);
    }
}

// ---- kernel: build pre-packed bf16-split B fragments ----
__global__ void k_wfrag(const float* __restrict__ Ws,
                        const float* __restrict__ Wr) {
    int i = blockIdx.x * blockDim.x + threadIdx.x;
    if (i >= 4 * 4 * 2 * 8 * 32) return;
    int lane = i & 31;
    int nt = (i >> 5) & 7;
    int ks = (i >> 8) & 1;
    int kc = (i >> 9) & 3;
    int wc = (i >> 11) & 3;
    int g = lane >> 2, t = lane & 3;
    int gn = wc * 64 + nt * 8 + g;          // output col 0..255
    int kg = kc * 32 + ks * 16 + 2 * t;     // k base

    const float* W = (gn < 128) ? Ws : Wr;
    int n = gn & 127;
    float w00 = W[kg * 128 + n],       w01 = W[(kg + 1) * 128 + n];
    float w10 = W[(kg + 8) * 128 + n], w11 = W[(kg + 9) * 128 + n];

    __nv_bfloat16 h00 = __float2bfloat16(w00), h01 = __float2bfloat16(w01);
    __nv_bfloat16 h10 = __float2bfloat16(w10), h11 = __float2bfloat16(w11);
    __nv_bfloat162 bh0 = {h00, h01}, bh1 = {h10, h11};
    __nv_bfloat162 bl0 = {__float2bfloat16(w00 - __bfloat162float(h00)),
                          __float2bfloat16(w01 - __bfloat162float(h01))};
    __nv_bfloat162 bl1 = {__float2bfloat16(w10 - __bfloat162float(h10)),
                          __float2bfloat16(w11 - __bfloat162float(h11))};
    uint4 v;
    v.x = *(unsigned*)&bh0; v.y = *(unsigned*)&bh1;
    v.z = *(unsigned*)&bl0; v.w = *(unsigned*)&bl1;
    g_Bfrag[i] = v;
}

// ---- mma / ldmatrix helpers ----
__device__ __forceinline__ void mma_bf16(float* c, const unsigned* a,
                                         unsigned b0, unsigned b1) {
    asm volatile(
        "mma.sync.aligned.m16n8k16.row.col.f32.bf16.bf16.f32 "
        "{%0,%1,%2,%3}, {%4,%5,%6,%7}, {%8,%9}, {%0,%1,%2,%3};"
        : "+f"(c[0]), "+f"(c[1]), "+f"(c[2]), "+f"(c[3])
        : "r"(a[0]), "r"(a[1]), "r"(a[2]), "r"(a[3]), "r"(b0), "r"(b1));
}
__device__ __forceinline__ void ldsm_x4(unsigned* d, unsigned addr) {
    asm volatile("ldmatrix.sync.aligned.m8n8.x4.shared.b16 {%0,%1,%2,%3}, [%4];"
                 : "=r"(d[0]), "=r"(d[1]), "=r"(d[2]), "=r"(d[3]) : "r"(addr));
}
__device__ __forceinline__ unsigned smem_u32(const void* p) {
    return (unsigned)__cvta_generic_to_shared(p);
}

// ---- kernel: tensor-core GEMM, bf16 3-term split ----
// C[50000,256] = A[50000,128] x [Ws|Wr][128,256]; CTA = 64 rows x 256 cols.
// B frags: 1 coalesced LDG.128/(nt). A frags: ldmatrix.x4 from smem.
#define SA 40   // smem row stride in bf16 elems (80B: 16B-aligned rows, conflict-free)
__global__ void __launch_bounds__(256, 2)
k_gemm_tc(const float* __restrict__ A,
          const float* __restrict__ Wsb, const float* __restrict__ Wrb) {
    __shared__ __nv_bfloat16 Ah[64 * SA];
    __shared__ __nv_bfloat16 Al[64 * SA];

    int tid  = threadIdx.x;
    int lane = tid & 31;
    int w    = tid >> 5;
    int wr   = w & 1;        // 2 row groups of 32
    int wc   = w >> 1;       // 4 col groups of 64
    int g    = lane >> 2;
    int t    = lane & 3;
    int row0 = blockIdx.x * 64;

    // A staging map: row = tid>>2, cols q8..q8+7 (2 float4)
    int srow = tid >> 2;
    int q8   = (tid & 3) * 8;
    int grow = row0 + srow;
    bool rok = grow < N_NODES;

    // ldmatrix lane address components: matrix m = lane>>3, row-in-matrix lane&7
    int lm_m   = lane >> 3;
    int lm_row = lane & 7;
    int lm_r   = (lm_m & 1) * 8 + lm_row;      // +8 rows for matrices 1,3
    int lm_c16 = (lm_m >> 1) * 16;             // +16B (8 cols) for matrices 2,3

    float acc[2][8][4];
#pragma unroll
    for (int rt = 0; rt < 2; rt++)
#pragma unroll
        for (int nt = 0; nt < 8; nt++)
#pragma unroll
            for (int j = 0; j < 4; j++) acc[rt][nt][j] = 0.f;

    for (int kc = 0; kc < 4; kc++) {
        int k0 = kc * 32;
        // stage + split A chunk [64][32]
#pragma unroll
        for (int v = 0; v < 2; v++) {
            float4 av = rok ? *(const float4*)(A + grow * 128 + k0 + q8 + v * 4)
                            : make_float4(0.f, 0.f, 0.f, 0.f);
            float h0 = __bfloat162float(__float2bfloat16(av.x));
            float h1 = __bfloat162float(__float2bfloat16(av.y));
            float h2 = __bfloat162float(__float2bfloat16(av.z));
            float h3 = __bfloat162float(__float2bfloat16(av.w));
            int base = srow * SA + q8 + v * 4;
            *(__nv_bfloat162*)&Ah[base]     = __floats2bfloat162_rn(h0, h1);
            *(__nv_bfloat162*)&Ah[base + 2] = __floats2bfloat162_rn(h2, h3);
            *(__nv_bfloat162*)&Al[base]     = __floats2bfloat162_rn(av.x - h0, av.y - h1);
            *(__nv_bfloat162*)&Al[base + 2] = __floats2bfloat162_rn(av.z - h2, av.w - h3);
        }
        __syncthreads();

        const uint4* bfrag = g_Bfrag + (((wc * 4 + kc) * 2) * 8) * 32 + lane;

#pragma unroll
        for (int ks = 0; ks < 2; ks++) {
            unsigned ah[2][4], al[2][4];
#pragma unroll
            for (int rt = 0; rt < 2; rt++) {
                int rbase = wr * 32 + rt * 16 + lm_r;
                unsigned ha = smem_u32(Ah) + rbase * (SA * 2) + ks * 32 + lm_c16;
                unsigned la = smem_u32(Al) + rbase * (SA * 2) + ks * 32 + lm_c16;
                ldsm_x4(ah[rt], ha);
                ldsm_x4(al[rt], la);
            }
            const uint4* bp = bfrag + ks * 8 * 32;
#pragma unroll
            for (int nt = 0; nt < 8; nt++) {
                uint4 b = bp[nt * 32];          // coalesced LDG.128
#pragma unroll
                for (int rt = 0; rt < 2; rt++) {
                    mma_bf16(acc[rt][nt], ah[rt], b.x, b.y);
                    mma_bf16(acc[rt][nt], ah[rt], b.z, b.w);
                    mma_bf16(acc[rt][nt], al[rt], b.x, b.y);
                }
            }
        }
        __syncthreads();
    }

    // epilogue: bias + store fp32 to g_S / g_R
#pragma unroll
    for (int rt = 0; rt < 2; rt++) {
        int r0 = row0 + wr * 32 + rt * 16 + g;
#pragma unroll
        for (int nt = 0; nt < 8; nt++) {
            int n = wc * 64 + nt * 8 + 2 * t;       // 0..255
            const float* bb = (n < 128) ? Wsb : Wrb;
            int nn = n & 127;
            float b0 = bb[nn], b1 = bb[nn + 1];
            float* O = (n < 128) ? g_S : g_R;
            if (r0 < N_NODES)
                *(float2*)(O + r0 * 128 + nn) =
                    make_float2(acc[rt][nt][0] + b0, acc[rt][nt][1] + b1);
            if (r0 + 8 < N_NODES)
                *(float2*)(O + (r0 + 8) * 128 + nn) =
                    make_float2(acc[rt][nt][2] + b0, acc[rt][nt][3] + b1);
        }
    }
}

// ---- kernel: offset reservation (warp scan + 1 atomic/warp) ----
__global__ void k_reserve() {
    int i = blockIdx.x * blockDim.x + threadIdx.x;
    int lane = threadIdx.x & 31;
    int c = (i < N_NODES) ? g_cnt[i] : 0;
    int x = c;
#pragma unroll
    for (int d = 1; d < 32; d <<= 1) {
        int y = __shfl_up_sync(0xFFFFFFFFu, x, d);
        if (lane >= d) x += y;
    }
    int total = __shfl_sync(0xFFFFFFFFu, x, 31);
    int base = 0;
    if (lane == 31) base = atomicAdd(&g_total, total);
    base = __shfl_sync(0xFFFFFFFFu, base, 31);
    if (i < N_NODES) {
        int off = base + x - c;
        g_off[i] = off;
        g_cur[i] = off;
    }
}

// ---- kernel: scatter sender ids into CSR buckets ----
__global__ void k_scatter(const int* __restrict__ senders,
                          const int* __restrict__ receivers) {
    int e = (blockIdx.x * blockDim.x + threadIdx.x) * 2;
    if (e < N_EDGES) {
        int2 r = *(const int2*)(receivers + e);
        int2 s = *(const int2*)(senders + e);
        int p0 = atomicAdd(&g_cur[r.x], 1);
        int p1 = atomicAdd(&g_cur[r.y], 1);
        g_csr[p0] = s.x;
        g_csr[p1] = s.y;
    }
}

// ---- kernel: fused softmax + aggregate, one warp per receiver node ----
__global__ void __launch_bounds__(256)
k_fused(const float* __restrict__ attn_k,
        const float* __restrict__ attn_b,
        float* __restrict__ out) {
    int warp = threadIdx.x >> 5;
    int lane = threadIdx.x & 31;
    int n = blockIdx.x * 8 + warp;
    if (n >= N_NODES) return;

    int off = g_off[n];
    int deg = g_cnt[n];

    float4 rv = ((const float4*)g_R)[n * 32 + lane];
    float4 ak = *(const float4*)(attn_k + (lane & 3) * 4);
    float  ab = attn_b[0];

    float4 acc = make_float4(0.f, 0.f, 0.f, 0.f);
    float  den = 0.f;

    if (deg > 0) {
        int s0 = g_csr[off];
        int s1 = (deg > 1) ? g_csr[off + 1] : 0;
        int s2 = (deg > 2) ? g_csr[off + 2] : 0;
        float4 sv  = ((const float4*)g_S)[s0 * 32 + lane];
        float4 svn = (deg > 1) ? ((const float4*)g_S)[s1 * 32 + lane]
                               : make_float4(0.f, 0.f, 0.f, 0.f);
        for (int i = 0; i < deg; i++) {
            float4 svn2 = make_float4(0.f, 0.f, 0.f, 0.f);
            if (i + 2 < deg) svn2 = ((const float4*)g_S)[s2 * 32 + lane];
            int s3 = (i + 3 < deg) ? g_csr[off + i + 3] : 0;

            float t = mish_f(sv.x + rv.x) * ak.x
                    + mish_f(sv.y + rv.y) * ak.y
                    + mish_f(sv.z + rv.z) * ak.z
                    + mish_f(sv.w + rv.w) * ak.w;
            t += __shfl_xor_sync(0xFFFFFFFFu, t, 1);
            t += __shfl_xor_sync(0xFFFFFFFFu, t, 2);
            float u = __expf(fminf(t + ab, 60.f));
            acc.x += u * sv.x;
            acc.y += u * sv.y;
            acc.z += u * sv.z;
            acc.w += u * sv.w;
            den += u;

            sv = svn; svn = svn2; s2 = s3;
        }
    }

    float inv = (deg > 0) ? __fdividef(1.f, den) : 0.f;
    ((float4*)out)[n * 32 + lane] =
        make_float4(acc.x * inv, acc.y * inv, acc.z * inv, acc.w * inv);
}

extern "C" void kernel_launch(void* const* d_in, const int* in_sizes, int n_in,
                              void* d_out, int out_size) {
    const float* nodes     = (const float*)d_in[0];
    const int*   senders   = (const int*)  d_in[1];
    const int*   receivers = (const int*)  d_in[2];
    const float* Ws_k      = (const float*)d_in[3];
    const float* Ws_b      = (const float*)d_in[4];
    const float* Wr_k      = (const float*)d_in[5];
    const float* Wr_b      = (const float*)d_in[6];
    const float* attn_k    = (const float*)d_in[7];
    const float* attn_b    = (const float*)d_in[8];
    float* out = (float*)d_out;

    k_zero<<<(N_NODES + 255) / 256, 256>>>();                          // 1
    k_hist<<<(N_EDGES / 2 + 255) / 256, 256>>>(receivers);             // 2
    k_wfrag<<<32, 256>>>(Ws_k, Wr_k);                                  // 3
    k_gemm_tc<<<(N_NODES + 63) / 64, 256>>>(nodes, Ws_b, Wr_b);        // 4 <- ncu slot
    k_reserve<<<(N_NODES + 255) / 256, 256>>>();                       // 5
    k_scatter<<<(N_EDGES / 2 + 255) / 256, 256>>>(senders, receivers); // 6
    k_fused<<<(N_NODES + 7) / 8, 256>>>(attn_k, attn_b, out);          // 7
}

// round 8
// speedup vs baseline: 3.4556x; 1.0645x over previous
#include <cuda_runtime.h>
#include <cuda_bf16.h>
#include <math.h>

#define N_NODES 50000
#define N_EDGES 800000
#define EMB 128
#define NH 8

// ---- scratch (static __device__, allocation-free) ----
__device__ float g_S[N_NODES * EMB];   // Ws(nodes)+b
__device__ float g_R[N_NODES * EMB];   // Wr(nodes)+b
__device__ int   g_csr[N_EDGES];
__device__ int   g_cnt[N_NODES];
__device__ int   g_off[N_NODES];
__device__ int   g_cur[N_NODES];
__device__ int   g_total;
// B fragments pre-packed per (wc,kc,ks,nt,lane): {bh0,bh1,bl0,bl1}
__device__ uint4 g_Bfrag[4 * 4 * 2 * 8 * 32];

__device__ __forceinline__ float mish_f(float x) {
    float u = __expf(fminf(x, 20.f));
    float v = u * u + 2.f * u;
    return x * __fdividef(v, v + 2.f);
}

// ---- kernel: zero counters ----
__global__ void k_zero() {
    int i = blockIdx.x * blockDim.x + threadIdx.x;
    if (i < N_NODES) g_cnt[i] = 0;
    if (i == 0) g_total = 0;
}

// ---- kernel: in-degree histogram (2 edges/thread) ----
__global__ void k_hist(const int* __restrict__ receivers) {
    int e = (blockIdx.x * blockDim.x + threadIdx.x) * 2;
    if (e < N_EDGES) {
        int2 r = *(const int2*)(receivers + e);
        atomicAdd(&g_cnt[r.x], 1);
        atomicAdd(&g_cnt[r.y], 1);
    }
}

// ---- kernel: build pre-packed bf16-split B fragments ----
__global__ void k_wfrag(const float* __restrict__ Ws,
                        const float* __restrict__ Wr) {
    int i = blockIdx.x * blockDim.x + threadIdx.x;
    if (i >= 4 * 4 * 2 * 8 * 32) return;
    int lane = i & 31;
    int nt = (i >> 5) & 7;
    int ks = (i >> 8) & 1;
    int kc = (i >> 9) & 3;
    int wc = (i >> 11) & 3;
    int g = lane >> 2, t = lane & 3;
    int gn = wc * 64 + nt * 8 + g;
    int kg = kc * 32 + ks * 16 + 2 * t;

    const float* W = (gn < 128) ? Ws : Wr;
    int n = gn & 127;
    float w00 = W[kg * 128 + n],       w01 = W[(kg + 1) * 128 + n];
    float w10 = W[(kg + 8) * 128 + n], w11 = W[(kg + 9) * 128 + n];

    __nv_bfloat16 h00 = __float2bfloat16(w00), h01 = __float2bfloat16(w01);
    __nv_bfloat16 h10 = __float2bfloat16(w10), h11 = __float2bfloat16(w11);
    __nv_bfloat162 bh0 = {h00, h01}, bh1 = {h10, h11};
    __nv_bfloat162 bl0 = {__float2bfloat16(w00 - __bfloat162float(h00)),
                          __float2bfloat16(w01 - __bfloat162float(h01))};
    __nv_bfloat162 bl1 = {__float2bfloat16(w10 - __bfloat162float(h10)),
                          __float2bfloat16(w11 - __bfloat162float(h11))};
    uint4 v;
    v.x = *(unsigned*)&bh0; v.y = *(unsigned*)&bh1;
    v.z = *(unsigned*)&bl0; v.w = *(unsigned*)&bl1;
    g_Bfrag[i] = v;
}

// ---- mma / ldmatrix helpers ----
__device__ __forceinline__ void mma_bf16(float* c, const unsigned* a,
                                         unsigned b0, unsigned b1) {
    asm volatile(
        "mma.sync.aligned.m16n8k16.row.col.f32.bf16.bf16.f32 "
        "{%0,%1,%2,%3}, {%4,%5,%6,%7}, {%8,%9}, {%0,%1,%2,%3};"
        : "+f"(c[0]), "+f"(c[1]), "+f"(c[2]), "+f"(c[3])
        : "r"(a[0]), "r"(a[1]), "r"(a[2]), "r"(a[3]), "r"(b0), "r"(b1));
}
__device__ __forceinline__ void ldsm_x4(unsigned* d, unsigned addr) {
    asm volatile("ldmatrix.sync.aligned.m8n8.x4.shared.b16 {%0,%1,%2,%3}, [%4];"
                 : "=r"(d[0]), "=r"(d[1]), "=r"(d[2]), "=r"(d[3]) : "r"(addr));
}
__device__ __forceinline__ unsigned smem_u32(const void* p) {
    return (unsigned)__cvta_generic_to_shared(p);
}

// ---- kernel: tensor-core GEMM, bf16 3-term split, double-buffered ----
#define SA 40
__global__ void __launch_bounds__(256, 2)
k_gemm_tc(const float* __restrict__ A,
          const float* __restrict__ Wsb, const float* __restrict__ Wrb) {
    __shared__ __nv_bfloat16 Ah[2][64 * SA];
    __shared__ __nv_bfloat16 Al[2][64 * SA];

    int tid  = threadIdx.x;
    int lane = tid & 31;
    int w    = tid >> 5;
    int wr   = w & 1;
    int wc   = w >> 1;
    int g    = lane >> 2;
    int t    = lane & 3;
    int row0 = blockIdx.x * 64;

    int srow = tid >> 2;
    int q8   = (tid & 3) * 8;
    int grow = row0 + srow;
    bool rok = grow < N_NODES;

    int lm_m   = lane >> 3;
    int lm_row = lane & 7;
    int lm_r   = (lm_m & 1) * 8 + lm_row;
    int lm_c16 = (lm_m >> 1) * 16;

    float acc[2][8][4];
#pragma unroll
    for (int rt = 0; rt < 2; rt++)
#pragma unroll
        for (int nt = 0; nt < 8; nt++)
#pragma unroll
            for (int j = 0; j < 4; j++) acc[rt][nt][j] = 0.f;

    float4 av0 = rok ? *(const float4*)(A + grow * 128 + q8)
                     : make_float4(0.f, 0.f, 0.f, 0.f);
    float4 av1 = rok ? *(const float4*)(A + grow * 128 + q8 + 4)
                     : make_float4(0.f, 0.f, 0.f, 0.f);

    int p = 0;
#pragma unroll
    for (int kc = 0; kc < 4; kc++) {
        // split + store staged chunk into buffer p
        {
            float4 av = av0;
#pragma unroll
            for (int v = 0; v < 2; v++) {
                float h0 = __bfloat162float(__float2bfloat16(av.x));
                float h1 = __bfloat162float(__float2bfloat16(av.y));
                float h2 = __bfloat162float(__float2bfloat16(av.z));
                float h3 = __bfloat162float(__float2bfloat16(av.w));
                int base = srow * SA + q8 + v * 4;
                *(__nv_bfloat162*)&Ah[p][base]     = __floats2bfloat162_rn(h0, h1);
                *(__nv_bfloat162*)&Ah[p][base + 2] = __floats2bfloat162_rn(h2, h3);
                *(__nv_bfloat162*)&Al[p][base]     = __floats2bfloat162_rn(av.x - h0, av.y - h1);
                *(__nv_bfloat162*)&Al[p][base + 2] = __floats2bfloat162_rn(av.z - h2, av.w - h3);
                av = av1;
            }
        }
        __syncthreads();
        if (kc < 3) {
            int k1 = (kc + 1) * 32;
            av0 = rok ? *(const float4*)(A + grow * 128 + k1 + q8)
                      : make_float4(0.f, 0.f, 0.f, 0.f);
            av1 = rok ? *(const float4*)(A + grow * 128 + k1 + q8 + 4)
                      : make_float4(0.f, 0.f, 0.f, 0.f);
        }

        const uint4* bfrag = g_Bfrag + (((wc * 4 + kc) * 2) * 8) * 32 + lane;
#pragma unroll
        for (int ks = 0; ks < 2; ks++) {
            unsigned ah[2][4], al[2][4];
#pragma unroll
            for (int rt = 0; rt < 2; rt++) {
                int rbase = wr * 32 + rt * 16 + lm_r;
                unsigned ha = smem_u32(Ah[p]) + rbase * (SA * 2) + ks * 32 + lm_c16;
                unsigned la = smem_u32(Al[p]) + rbase * (SA * 2) + ks * 32 + lm_c16;
                ldsm_x4(ah[rt], ha);
                ldsm_x4(al[rt], la);
            }
            const uint4* bp = bfrag + ks * 8 * 32;
#pragma unroll
            for (int nt = 0; nt < 8; nt++) {
                uint4 b = bp[nt * 32];
#pragma unroll
                for (int rt = 0; rt < 2; rt++) {
                    mma_bf16(acc[rt][nt], ah[rt], b.x, b.y);
                    mma_bf16(acc[rt][nt], ah[rt], b.z, b.w);
                    mma_bf16(acc[rt][nt], al[rt], b.x, b.y);
                }
            }
        }
        p ^= 1;
    }

#pragma unroll
    for (int rt = 0; rt < 2; rt++) {
        int r0 = row0 + wr * 32 + rt * 16 + g;
#pragma unroll
        for (int nt = 0; nt < 8; nt++) {
            int n = wc * 64 + nt * 8 + 2 * t;
            const float* bb = (n < 128) ? Wsb : Wrb;
            int nn = n & 127;
            float b0 = bb[nn], b1 = bb[nn + 1];
            float* O = (n < 128) ? g_S : g_R;
            if (r0 < N_NODES)
                *(float2*)(O + r0 * 128 + nn) =
                    make_float2(acc[rt][nt][0] + b0, acc[rt][nt][1] + b1);
            if (r0 + 8 < N_NODES)
                *(float2*)(O + (r0 + 8) * 128 + nn) =
                    make_float2(acc[rt][nt][2] + b0, acc[rt][nt][3] + b1);
        }
    }
}

// ---- kernel: offset reservation ----
__global__ void k_reserve() {
    int i = blockIdx.x * blockDim.x + threadIdx.x;
    int lane = threadIdx.x & 31;
    int c = (i < N_NODES) ? g_cnt[i] : 0;
    int x = c;
#pragma unroll
    for (int d = 1; d < 32; d <<= 1) {
        int y = __shfl_up_sync(0xFFFFFFFFu, x, d);
        if (lane >= d) x += y;
    }
    int total = __shfl_sync(0xFFFFFFFFu, x, 31);
    int base = 0;
    if (lane == 31) base = atomicAdd(&g_total, total);
    base = __shfl_sync(0xFFFFFFFFu, base, 31);
    if (i < N_NODES) {
        int off = base + x - c;
        g_off[i] = off;
        g_cur[i] = off;
    }
}

// ---- kernel: scatter sender ids into CSR buckets ----
__global__ void k_scatter(const int* __restrict__ senders,
                          const int* __restrict__ receivers) {
    int e = (blockIdx.x * blockDim.x + threadIdx.x) * 2;
    if (e < N_EDGES) {
        int2 r = *(const int2*)(receivers + e);
        int2 s = *(const int2*)(senders + e);
        int p0 = atomicAdd(&g_cur[r.x], 1);
        int p1 = atomicAdd(&g_cur[r.y], 1);
        g_csr[p0] = s.x;
        g_csr[p1] = s.y;
    }
}

// ---- kernel: fused softmax + aggregate, one warp per receiver node ----
__global__ void __launch_bounds__(256)
k_fused(const float* __restrict__ attn_k,
        const float* __restrict__ attn_b,
        float* __restrict__ out) {
    int warp = threadIdx.x >> 5;
    int lane = threadIdx.x & 31;
    int n = blockIdx.x * 8 + warp;
    if (n >= N_NODES) return;

    int off = g_off[n];
    int deg = g_cnt[n];

    float4 rv = ((const float4*)g_R)[n * 32 + lane];
    float4 ak = *(const float4*)(attn_k + (lane & 3) * 4);
    float  ab = attn_b[0];

    float4 acc = make_float4(0.f, 0.f, 0.f, 0.f);
    float  den = 0.f;

    if (deg > 0) {
        int s0 = g_csr[off];
        int s1 = (deg > 1) ? g_csr[off + 1] : 0;
        int s2 = (deg > 2) ? g_csr[off + 2] : 0;
        float4 sv  = ((const float4*)g_S)[s0 * 32 + lane];
        float4 svn = (deg > 1) ? ((const float4*)g_S)[s1 * 32 + lane]
                               : make_float4(0.f, 0.f, 0.f, 0.f);
        for (int i = 0; i < deg; i++) {
            float4 svn2 = make_float4(0.f, 0.f, 0.f, 0.f);
            if (i + 2 < deg) svn2 = ((const float4*)g_S)[s2 * 32 + lane];
            int s3 = (i + 3 < deg) ? g_csr[off + i + 3] : 0;

            float t = mish_f(sv.x + rv.x) * ak.x
                    + mish_f(sv.y + rv.y) * ak.y
                    + mish_f(sv.z + rv.z) * ak.z
                    + mish_f(sv.w + rv.w) * ak.w;
            t += __shfl_xor_sync(0xFFFFFFFFu, t, 1);
            t += __shfl_xor_sync(0xFFFFFFFFu, t, 2);
            float u = __expf(fminf(t + ab, 60.f));
            acc.x += u * sv.x;
            acc.y += u * sv.y;
            acc.z += u * sv.z;
            acc.w += u * sv.w;
            den += u;

            sv = svn; svn = svn2; s2 = s3;
        }
    }

    float inv = (deg > 0) ? __fdividef(1.f, den) : 0.f;
    ((float4*)out)[n * 32 + lane] =
        make_float4(acc.x * inv, acc.y * inv, acc.z * inv, acc.w * inv);
}

extern "C" void kernel_launch(void* const* d_in, const int* in_sizes, int n_in,
                              void* d_out, int out_size) {
    const float* nodes     = (const float*)d_in[0];
    const int*   senders   = (const int*)  d_in[1];
    const int*   receivers = (const int*)  d_in[2];
    const float* Ws_k      = (const float*)d_in[3];
    const float* Ws_b      = (const float*)d_in[4];
    const float* Wr_k      = (const float*)d_in[5];
    const float* Wr_b      = (const float*)d_in[6];
    const float* attn_k    = (const float*)d_in[7];
    const float* attn_b    = (const float*)d_in[8];
    float* out = (float*)d_out;

    // one-time stream/event creation on the first (uncaptured) call;
    // no device memory involved, identical launch pattern every call.
    static cudaStream_t s2 = []() {
        cudaStream_t s; cudaStreamCreateWithFlags(&s, cudaStreamNonBlocking);
        return s;
    }();
    static cudaEvent_t evA = []() {
        cudaEvent_t e; cudaEventCreateWithFlags(&e, cudaEventDisableTiming);
        return e;
    }();
    static cudaEvent_t evB = []() {
        cudaEvent_t e; cudaEventCreateWithFlags(&e, cudaEventDisableTiming);
        return e;
    }();

    // fork: CSR-build branch on s2, GEMM branch on the main (capture) stream
    cudaEventRecord(evA, 0);
    cudaStreamWaitEvent(s2, evA, 0);

    k_zero<<<(N_NODES + 255) / 256, 256, 0, s2>>>();
    k_hist<<<(N_EDGES / 2 + 255) / 256, 256, 0, s2>>>(receivers);
    k_reserve<<<(N_NODES + 255) / 256, 256, 0, s2>>>();
    k_scatter<<<(N_EDGES / 2 + 255) / 256, 256, 0, s2>>>(senders, receivers);
    cudaEventRecord(evB, s2);

    k_wfrag<<<32, 256>>>(Ws_k, Wr_k);
    k_gemm_tc<<<(N_NODES + 63) / 64, 256>>>(nodes, Ws_b, Wr_b);

    // join, then the fused consumer
    cudaStreamWaitEvent(0, evB, 0);
    k_fused<<<(N_NODES + 7) / 8, 256>>>(attn_k, attn_b, out);
}

// round 9
// speedup vs baseline: 3.5440x; 1.0256x over previous
#include <cuda_runtime.h>
#include <cuda_bf16.h>
#include <math.h>

#define N_NODES 50000
#define N_EDGES 800000
#define EMB 128
#define NH 8

typedef unsigned long long u64;

// ---- scratch (static __device__, allocation-free) ----
__device__ float g_S[N_NODES * EMB];   // Ws(nodes)+b
__device__ float g_R[N_NODES * EMB];   // Wr(nodes)+b
__device__ int   g_csr[N_EDGES];
__device__ int   g_cnt[N_NODES];
__device__ int   g_off[N_NODES];
__device__ int   g_cur[N_NODES];
__device__ int   g_total;
__device__ uint4 g_Bfrag[4 * 4 * 2 * 8 * 32];

// ---- f32x2 packed helpers ----
__device__ __forceinline__ u64 pk2(float lo, float hi) {
    u64 r; asm("mov.b64 %0, {%1, %2};" : "=l"(r) : "f"(lo), "f"(hi)); return r;
}
__device__ __forceinline__ void upk2(float& lo, float& hi, u64 v) {
    asm("mov.b64 {%0, %1}, %2;" : "=f"(lo), "=f"(hi) : "l"(v));
}
__device__ __forceinline__ u64 add2(u64 a, u64 b) {
    u64 r; asm("add.rn.f32x2 %0, %1, %2;" : "=l"(r) : "l"(a), "l"(b)); return r;
}
__device__ __forceinline__ u64 mul2(u64 a, u64 b) {
    u64 r; asm("mul.rn.f32x2 %0, %1, %2;" : "=l"(r) : "l"(a), "l"(b)); return r;
}
__device__ __forceinline__ u64 fma2v(u64 a, u64 b, u64 c) {
    u64 r; asm("fma.rn.f32x2 %0, %1, %2, %3;" : "=l"(r) : "l"(a), "l"(b), "l"(c)); return r;
}
__device__ __forceinline__ float ex2f(float x) {
    float r; asm("ex2.approx.f32 %0, %1;" : "=f"(r) : "f"(x)); return r;
}
__device__ __forceinline__ float rcpf(float x) {
    float r; asm("rcp.approx.f32 %0, %1;" : "=f"(r) : "f"(x)); return r;
}
#define L2E 1.4426950408889634f

// ---- kernel: zero counters ----
__global__ void k_zero() {
    int i = blockIdx.x * blockDim.x + threadIdx.x;
    if (i < N_NODES) g_cnt[i] = 0;
    if (i == 0) g_total = 0;
}

// ---- kernel: in-degree histogram (2 edges/thread) ----
__global__ void k_hist(const int* __restrict__ receivers) {
    int e = (blockIdx.x * blockDim.x + threadIdx.x) * 2;
    if (e < N_EDGES) {
        int2 r = *(const int2*)(receivers + e);
        atomicAdd(&g_cnt[r.x], 1);
        atomicAdd(&g_cnt[r.y], 1);
    }
}

// ---- kernel: build pre-packed bf16-split B fragments ----
__global__ void k_wfrag(const float* __restrict__ Ws,
                        const float* __restrict__ Wr) {
    int i = blockIdx.x * blockDim.x + threadIdx.x;
    if (i >= 4 * 4 * 2 * 8 * 32) return;
    int lane = i & 31;
    int nt = (i >> 5) & 7;
    int ks = (i >> 8) & 1;
    int kc = (i >> 9) & 3;
    int wc = (i >> 11) & 3;
    int g = lane >> 2, t = lane & 3;
    int gn = wc * 64 + nt * 8 + g;
    int kg = kc * 32 + ks * 16 + 2 * t;

    const float* W = (gn < 128) ? Ws : Wr;
    int n = gn & 127;
    float w00 = W[kg * 128 + n],       w01 = W[(kg + 1) * 128 + n];
    float w10 = W[(kg + 8) * 128 + n], w11 = W[(kg + 9) * 128 + n];

    __nv_bfloat16 h00 = __float2bfloat16(w00), h01 = __float2bfloat16(w01);
    __nv_bfloat16 h10 = __float2bfloat16(w10), h11 = __float2bfloat16(w11);
    __nv_bfloat162 bh0 = {h00, h01}, bh1 = {h10, h11};
    __nv_bfloat162 bl0 = {__float2bfloat16(w00 - __bfloat162float(h00)),
                          __float2bfloat16(w01 - __bfloat162float(h01))};
    __nv_bfloat162 bl1 = {__float2bfloat16(w10 - __bfloat162float(h10)),
                          __float2bfloat16(w11 - __bfloat162float(h11))};
    uint4 v;
    v.x = *(unsigned*)&bh0; v.y = *(unsigned*)&bh1;
    v.z = *(unsigned*)&bl0; v.w = *(unsigned*)&bl1;
    g_Bfrag[i] = v;
}

// ---- mma / ldmatrix helpers ----
__device__ __forceinline__ void mma_bf16(float* c, const unsigned* a,
                                         unsigned b0, unsigned b1) {
    asm volatile(
        "mma.sync.aligned.m16n8k16.row.col.f32.bf16.bf16.f32 "
        "{%0,%1,%2,%3}, {%4,%5,%6,%7}, {%8,%9}, {%0,%1,%2,%3};"
        : "+f"(c[0]), "+f"(c[1]), "+f"(c[2]), "+f"(c[3])
        : "r"(a[0]), "r"(a[1]), "r"(a[2]), "r"(a[3]), "r"(b0), "r"(b1));
}
__device__ __forceinline__ void ldsm_x4(unsigned* d, unsigned addr) {
    asm volatile("ldmatrix.sync.aligned.m8n8.x4.shared.b16 {%0,%1,%2,%3}, [%4];"
                 : "=r"(d[0]), "=r"(d[1]), "=r"(d[2]), "=r"(d[3]) : "r"(addr));
}
__device__ __forceinline__ unsigned smem_u32(const void* p) {
    return (unsigned)__cvta_generic_to_shared(p);
}

// ---- kernel: tensor-core GEMM, bf16 3-term split, double-buffered ----
#define SA 40
__global__ void __launch_bounds__(256, 2)
k_gemm_tc(const float* __restrict__ A,
          const float* __restrict__ Wsb, const float* __restrict__ Wrb) {
    __shared__ __nv_bfloat16 Ah[2][64 * SA];
    __shared__ __nv_bfloat16 Al[2][64 * SA];

    int tid  = threadIdx.x;
    int lane = tid & 31;
    int w    = tid >> 5;
    int wr   = w & 1;
    int wc   = w >> 1;
    int g    = lane >> 2;
    int t    = lane & 3;
    int row0 = blockIdx.x * 64;

    int srow = tid >> 2;
    int q8   = (tid & 3) * 8;
    int grow = row0 + srow;
    bool rok = grow < N_NODES;

    int lm_m   = lane >> 3;
    int lm_row = lane & 7;
    int lm_r   = (lm_m & 1) * 8 + lm_row;
    int lm_c16 = (lm_m >> 1) * 16;

    float acc[2][8][4];
#pragma unroll
    for (int rt = 0; rt < 2; rt++)
#pragma unroll
        for (int nt = 0; nt < 8; nt++)
#pragma unroll
            for (int j = 0; j < 4; j++) acc[rt][nt][j] = 0.f;

    float4 av0 = rok ? *(const float4*)(A + grow * 128 + q8)
                     : make_float4(0.f, 0.f, 0.f, 0.f);
    float4 av1 = rok ? *(const float4*)(A + grow * 128 + q8 + 4)
                     : make_float4(0.f, 0.f, 0.f, 0.f);

    int p = 0;
#pragma unroll
    for (int kc = 0; kc < 4; kc++) {
        {
            float4 av = av0;
#pragma unroll
            for (int v = 0; v < 2; v++) {
                float h0 = __bfloat162float(__float2bfloat16(av.x));
                float h1 = __bfloat162float(__float2bfloat16(av.y));
                float h2 = __bfloat162float(__float2bfloat16(av.z));
                float h3 = __bfloat162float(__float2bfloat16(av.w));
                int base = srow * SA + q8 + v * 4;
                *(__nv_bfloat162*)&Ah[p][base]     = __floats2bfloat162_rn(h0, h1);
                *(__nv_bfloat162*)&Ah[p][base + 2] = __floats2bfloat162_rn(h2, h3);
                *(__nv_bfloat162*)&Al[p][base]     = __floats2bfloat162_rn(av.x - h0, av.y - h1);
                *(__nv_bfloat162*)&Al[p][base + 2] = __floats2bfloat162_rn(av.z - h2, av.w - h3);
                av = av1;
            }
        }
        __syncthreads();
        if (kc < 3) {
            int k1 = (kc + 1) * 32;
            av0 = rok ? *(const float4*)(A + grow * 128 + k1 + q8)
                      : make_float4(0.f, 0.f, 0.f, 0.f);
            av1 = rok ? *(const float4*)(A + grow * 128 + k1 + q8 + 4)
                      : make_float4(0.f, 0.f, 0.f, 0.f);
        }

        const uint4* bfrag = g_Bfrag + (((wc * 4 + kc) * 2) * 8) * 32 + lane;
#pragma unroll
        for (int ks = 0; ks < 2; ks++) {
            unsigned ah[2][4], al[2][4];
#pragma unroll
            for (int rt = 0; rt < 2; rt++) {
                int rbase = wr * 32 + rt * 16 + lm_r;
                unsigned ha = smem_u32(Ah[p]) + rbase * (SA * 2) + ks * 32 + lm_c16;
                unsigned la = smem_u32(Al[p]) + rbase * (SA * 2) + ks * 32 + lm_c16;
                ldsm_x4(ah[rt], ha);
                ldsm_x4(al[rt], la);
            }
            const uint4* bp = bfrag + ks * 8 * 32;
#pragma unroll
            for (int nt = 0; nt < 8; nt++) {
                uint4 b = bp[nt * 32];
#pragma unroll
                for (int rt = 0; rt < 2; rt++) {
                    mma_bf16(acc[rt][nt], ah[rt], b.x, b.y);
                    mma_bf16(acc[rt][nt], ah[rt], b.z, b.w);
                    mma_bf16(acc[rt][nt], al[rt], b.x, b.y);
                }
            }
        }
        p ^= 1;
    }

#pragma unroll
    for (int rt = 0; rt < 2; rt++) {
        int r0 = row0 + wr * 32 + rt * 16 + g;
#pragma unroll
        for (int nt = 0; nt < 8; nt++) {
            int n = wc * 64 + nt * 8 + 2 * t;
            const float* bb = (n < 128) ? Wsb : Wrb;
            int nn = n & 127;
            float b0 = bb[nn], b1 = bb[nn + 1];
            float* O = (n < 128) ? g_S : g_R;
            if (r0 < N_NODES)
                *(float2*)(O + r0 * 128 + nn) =
                    make_float2(acc[rt][nt][0] + b0, acc[rt][nt][1] + b1);
            if (r0 + 8 < N_NODES)
                *(float2*)(O + (r0 + 8) * 128 + nn) =
                    make_float2(acc[rt][nt][2] + b0, acc[rt][nt][3] + b1);
        }
    }
}

// ---- kernel: offset reservation ----
__global__ void k_reserve() {
    int i = blockIdx.x * blockDim.x + threadIdx.x;
    int lane = threadIdx.x & 31;
    int c = (i < N_NODES) ? g_cnt[i] : 0;
    int x = c;
#pragma unroll
    for (int d = 1; d < 32; d <<= 1) {
        int y = __shfl_up_sync(0xFFFFFFFFu, x, d);
        if (lane >= d) x += y;
    }
    int total = __shfl_sync(0xFFFFFFFFu, x, 31);
    int base = 0;
    if (lane == 31) base = atomicAdd(&g_total, total);
    base = __shfl_sync(0xFFFFFFFFu, base, 31);
    if (i < N_NODES) {
        int off = base + x - c;
        g_off[i] = off;
        g_cur[i] = off;
    }
}

// ---- kernel: scatter sender ids into CSR buckets ----
__global__ void k_scatter(const int* __restrict__ senders,
                          const int* __restrict__ receivers) {
    int e = (blockIdx.x * blockDim.x + threadIdx.x) * 2;
    if (e < N_EDGES) {
        int2 r = *(const int2*)(receivers + e);
        int2 s = *(const int2*)(senders + e);
        int p0 = atomicAdd(&g_cur[r.x], 1);
        int p1 = atomicAdd(&g_cur[r.y], 1);
        g_csr[p0] = s.x;
        g_csr[p1] = s.y;
    }
}

// ---- kernel: fused softmax + aggregate, one warp per receiver node ----
// Combined-reciprocal mish (1 RCP per lane-edge instead of 4) + f32x2 packed
// elementwise chain. u = e^min(x,10) (tanh saturates: err < 1e-7 abs).
__global__ void __launch_bounds__(256)
k_fused(const float* __restrict__ attn_k,
        const float* __restrict__ attn_b,
        float* __restrict__ out) {
    int warp = threadIdx.x >> 5;
    int lane = threadIdx.x & 31;
    int n = blockIdx.x * 8 + warp;
    if (n >= N_NODES) return;

    int off = g_off[n];
    int deg = g_cnt[n];

    float4 rv = ((const float4*)g_R)[n * 32 + lane];
    float4 ak = *(const float4*)(attn_k + (lane & 3) * 4);
    float  ab = attn_b[0];

    u64 rv01 = pk2(rv.x, rv.y), rv23 = pk2(rv.z, rv.w);
    u64 ak01 = pk2(ak.x, ak.y), ak23 = pk2(ak.z, ak.w);
    const u64 TWO2 = 0x4000000040000000ULL;   // (2.0f, 2.0f)

    u64 acc01 = 0ULL, acc23 = 0ULL;
    float den = 0.f;

    if (deg > 0) {
        int s = g_csr[off];
        float4 sv = ((const float4*)g_S)[s * 32 + lane];
        for (int i = 0; i < deg; i++) {
            float4 svn;
            if (i + 1 < deg) {
                int s2 = g_csr[off + i + 1];
                svn = ((const float4*)g_S)[s2 * 32 + lane];
            }
            u64 sv01 = pk2(sv.x, sv.y), sv23 = pk2(sv.z, sv.w);
            u64 xs01 = add2(sv01, rv01), xs23 = add2(sv23, rv23);
            float x0, x1, x2, x3;
            upk2(x0, x1, xs01); upk2(x2, x3, xs23);

            float u0 = ex2f(fminf(x0, 10.f) * L2E);
            float u1 = ex2f(fminf(x1, 10.f) * L2E);
            float u2 = ex2f(fminf(x2, 10.f) * L2E);
            float u3 = ex2f(fminf(x3, 10.f) * L2E);

            u64 U01 = pk2(u0, u1), U23 = pk2(u2, u3);
            u64 T01 = add2(U01, TWO2), T23 = add2(U23, TWO2);
            u64 V01 = mul2(U01, T01), V23 = mul2(U23, T23);
            u64 D01 = add2(V01, TWO2), D23 = add2(V23, TWO2);
            float d0, d1, d2, d3;
            upk2(d0, d1, D01); upk2(d2, d3, D23);

            float p12 = d0 * d1, p34 = d2 * d3;
            float invD = rcpf(p12 * p34);
            u64 Q01 = pk2(d1 * p34, d0 * p34);
            u64 Q23 = pk2(d3 * p12, d2 * p12);
            u64 N01 = mul2(V01, Q01), N23 = mul2(V23, Q23);
            u64 XA01 = mul2(xs01, ak01), XA23 = mul2(xs23, ak23);
            u64 M = add2(mul2(XA01, N01), mul2(XA23, N23));
            float ma, mb; upk2(ma, mb, M);
            float t = (ma + mb) * invD;

            t += __shfl_xor_sync(0xFFFFFFFFu, t, 1);
            t += __shfl_xor_sync(0xFFFFFFFFu, t, 2);
            float ue = ex2f(fminf(t + ab, 60.f) * L2E);

            u64 UU = pk2(ue, ue);
            acc01 = fma2v(UU, sv01, acc01);
            acc23 = fma2v(UU, sv23, acc23);
            den += ue;

            sv = svn;
        }
    }

    float inv = (deg > 0) ? __fdividef(1.f, den) : 0.f;
    float a0, a1, a2, a3;
    upk2(a0, a1, acc01); upk2(a2, a3, acc23);
    ((float4*)out)[n * 32 + lane] =
        make_float4(a0 * inv, a1 * inv, a2 * inv, a3 * inv);
}

extern "C" void kernel_launch(void* const* d_in, const int* in_sizes, int n_in,
                              void* d_out, int out_size) {
    const float* nodes     = (const float*)d_in[0];
    const int*   senders   = (const int*)  d_in[1];
    const int*   receivers = (const int*)  d_in[2];
    const float* Ws_k      = (const float*)d_in[3];
    const float* Ws_b      = (const float*)d_in[4];
    const float* Wr_k      = (const float*)d_in[5];
    const float* Wr_b      = (const float*)d_in[6];
    const float* attn_k    = (const float*)d_in[7];
    const float* attn_b    = (const float*)d_in[8];
    float* out = (float*)d_out;

    static cudaStream_t s2 = []() {
        cudaStream_t s; cudaStreamCreateWithFlags(&s, cudaStreamNonBlocking);
        return s;
    }();
    static cudaEvent_t evA = []() {
        cudaEvent_t e; cudaEventCreateWithFlags(&e, cudaEventDisableTiming);
        return e;
    }();
    static cudaEvent_t evB = []() {
        cudaEvent_t e; cudaEventCreateWithFlags(&e, cudaEventDisableTiming);
        return e;
    }();

    cudaEventRecord(evA, 0);
    cudaStreamWaitEvent(s2, evA, 0);

    // call order chosen so k_gemm_tc is the 4th kernel launch (ncu slot)
    k_zero<<<(N_NODES + 255) / 256, 256, 0, s2>>>();                   // 1
    k_hist<<<(N_EDGES / 2 + 255) / 256, 256, 0, s2>>>(receivers);      // 2
    k_wfrag<<<32, 256>>>(Ws_k, Wr_k);                                  // 3
    k_gemm_tc<<<(N_NODES + 63) / 64, 256>>>(nodes, Ws_b, Wr_b);        // 4
    k_reserve<<<(N_NODES + 255) / 256, 256, 0, s2>>>();                // 5
    k_scatter<<<(N_EDGES / 2 + 255) / 256, 256, 0, s2>>>(senders, receivers); // 6
    cudaEventRecord(evB, s2);

    cudaStreamWaitEvent(0, evB, 0);
    k_fused<<<(N_NODES + 7) / 8, 256>>>(attn_k, attn_b, out);          // 7
}